// round 9
// baseline (speedup 1.0000x reference)
#include <cuda_runtime.h>
#include <cuda_bf16.h>
#include <cstdint>

#define NB 32
#define NC 64
#define NS 128
#define NZ 64
#define ND 256
#define VO 5000
#define VOP 5120

typedef __nv_bfloat16 bf16;

// ---- pair-kernel smem byte offsets ----
#define OB_AM    0         // 67584 B
#define OB_BM    67584     // 33792 B
#define OB_BG2T  0         // 36864 B
#define OB_STG7  36864     // 69632 B
#define OB_E     106496    // e fp32 [128][68] = 34816
#define OB_BETA  141312    // beta bf16 [128][72] = 18432
#define OB_ALPT  159744    // alphaT bf16 [64][136] = 17408
#define OB_CID   177152    // 64 ints
#define OB_HW    177408    // 512 fp32
#define OB_RED   179456    // 16 fp32
#define SMEM_PAIR 179520

// pitches (elements)
#define P_AM   264
#define P_BM   264
#define P_E    68
#define P_BETA 72
#define P_BG2T 72
#define P_ALPT 136
#define P_STG7 136

// ---------------- device scratch ----------------
__device__ bf16  g_am  [NB*NS*ND];   // bf16 relu(a@FW+Fb)       [b][s][k]
__device__ float g_aG1 [NB*NS*ND];   // exact a@GW1+Gb           [b][s][g]
__device__ bf16  g_aG2T[NB*ND*NS];   // bf16 (a@GW2)^T           [b][g][s]
__device__ bf16  g_bm  [VOP*ND];     // bf16 relu(EmbB@FW+Fb)    [v][k]
__device__ float g_bg1 [VOP*ND];     // exact EmbB@GW1+Gb        [v][g]
__device__ bf16  g_bg2 [VOP*ND];     // bf16 EmbB@GW2            [v][g]

// ---------------- helpers ----------------
__device__ __forceinline__ uint32_t ldb(const bf16* p){
    return *reinterpret_cast<const uint32_t*>(p);
}
__device__ __forceinline__ uint32_t pkf(float a, float b){
    __nv_bfloat162 t = __floats2bfloat162_rn(a, b);
    return *reinterpret_cast<uint32_t*>(&t);
}
__device__ __forceinline__ uint32_t pkh(bf16 a, bf16 b){
    __nv_bfloat162 t = __halves2bfloat162(a, b);
    return *reinterpret_cast<uint32_t*>(&t);
}
__device__ __forceinline__ void mmab(float* d,
    uint32_t a0,uint32_t a1,uint32_t a2,uint32_t a3, uint32_t b0,uint32_t b1){
    asm volatile("mma.sync.aligned.m16n8k16.row.col.f32.bf16.bf16.f32 "
        "{%0,%1,%2,%3}, {%4,%5,%6,%7}, {%8,%9}, {%0,%1,%2,%3};\n"
        : "+f"(d[0]),"+f"(d[1]),"+f"(d[2]),"+f"(d[3])
        : "r"(a0),"r"(a1),"r"(a2),"r"(a3),"r"(b0),"r"(b1));
}

// =========================================================================
// Tables kernel (exact fp32 FFMA; bf16/fp32 outputs). 64-row tiles.
// __launch_bounds__(256, 2) pins regs <= 128 so 2 CTAs/SM are resident.
// grid=(12, 144): y<64 -> a-side (b=y>>1, half=y&1); else vocab tile rt=y-64.
// m = chunk>>2: 0 F+relu (bf16), 1 GW1+Gb (fp32), 2 GW2 (bf16; a-side -> g_aG2T)
// =========================================================================
__global__ void __launch_bounds__(256, 2) tables_kernel(
    const int*   __restrict__ inptensor,
    const float* __restrict__ EmbA,
    const float* __restrict__ EmbB,
    const float* __restrict__ FW,
    const float* __restrict__ Fb,
    const float* __restrict__ GW,
    const float* __restrict__ Gb)
{
    extern __shared__ float sm[];
    float* a_tile = sm;              // 64*257
    float* wst    = sm + 64*257;     // 16*64

    const int y     = blockIdx.y;
    const int chunk = blockIdx.x;
    const int m     = chunk >> 2;
    const int gbase = (chunk & 3) * 64;
    const int tid   = threadIdx.x;
    const bool aside = (y < 2*NB);

    if (aside) {
        const int b = y >> 1, sh = (y & 1) * 64;
        for (int s = 0; s < 64; s++) {
            int idx = __ldg(&inptensor[b*NS + sh + s]);
            a_tile[s*257 + tid] = __ldg(&EmbA[(size_t)idx*ND + tid]);
        }
    } else {
        const int rt = y - 2*NB;
        for (int s = 0; s < 64; s++) {
            int row = rt*64 + s;
            int rr = (row < VO) ? row : 0;
            a_tile[s*257 + tid] = __ldg(&EmbB[(size_t)rr*ND + tid]);
        }
    }
    __syncthreads();

    const int tr = tid >> 3;   // 0..31 (row group)
    const int tc = tid & 7;    // 0..7  (8 consecutive g per thread)

    float acc[2][8];
    #pragma unroll
    for (int i = 0; i < 2; i++)
        #pragma unroll
        for (int j = 0; j < 8; j++) acc[i][j] = 0.f;

    for (int k0 = 0; k0 < ND; k0 += 16) {
        #pragma unroll
        for (int t = 0; t < 4; t++) {
            int idx2 = tid + 256*t;
            int kk = idx2 >> 6, gg = idx2 & 63;
            int row = k0 + kk + (m == 2 ? 256 : 0);
            const float* Wsrc = (m == 0) ? FW : GW;
            wst[idx2] = __ldg(&Wsrc[row*256 + gbase + gg]);
        }
        __syncthreads();
        #pragma unroll
        for (int kk = 0; kk < 16; kk++) {
            float av0 = a_tile[tr*257 + k0 + kk];
            float av1 = a_tile[(tr + 32)*257 + k0 + kk];
            const float4* wp = (const float4*)(wst + kk*64 + tc*8);
            float4 w0 = wp[0], w1 = wp[1];
            acc[0][0] += av0*w0.x; acc[1][0] += av1*w0.x;
            acc[0][1] += av0*w0.y; acc[1][1] += av1*w0.y;
            acc[0][2] += av0*w0.z; acc[1][2] += av1*w0.z;
            acc[0][3] += av0*w0.w; acc[1][3] += av1*w0.w;
            acc[0][4] += av0*w1.x; acc[1][4] += av1*w1.x;
            acc[0][5] += av0*w1.y; acc[1][5] += av1*w1.y;
            acc[0][6] += av0*w1.z; acc[1][6] += av1*w1.z;
            acc[0][7] += av0*w1.w; acc[1][7] += av1*w1.w;
        }
        __syncthreads();
    }

    const int b_  = y >> 1, sh = (y & 1) * 64;
    const int rt  = y - 2*NB;

    if (m == 2 && aside) {
        // transpose through smem (a_tile dead), then coalesced store to g_aG2T
        bf16* tbuf = (bf16*)a_tile;              // [64 g][66 s] bf16, pitch 66
        #pragma unroll
        for (int i = 0; i < 2; i++) {
            int row = tr + 32*i;                 // local s (0..63)
            #pragma unroll
            for (int j = 0; j < 8; j++)
                tbuf[(tc*8 + j)*66 + row] = __float2bfloat16_rn(acc[i][j]);
        }
        __syncthreads();
        // smem side 4-byte aligned (pitch 66 bf16 = 132 B) -> read as u32
        int gl = tid >> 2;                       // 0..63
        int sc = (tid & 3) * 16;
        const uint32_t* src = (const uint32_t*)(tbuf + gl*66 + sc);
        uint32_t v0=src[0],v1=src[1],v2=src[2],v3=src[3];
        uint32_t v4=src[4],v5=src[5],v6=src[6],v7=src[7];
        uint4* dst = (uint4*)(g_aG2T + ((size_t)b_*ND + gbase + gl)*NS + sh + sc);
        dst[0] = make_uint4(v0,v1,v2,v3);
        dst[1] = make_uint4(v4,v5,v6,v7);
        return;
    }

    #pragma unroll
    for (int i = 0; i < 2; i++) {
        int row = aside ? (sh + tr + 32*i) : (rt*64 + tr + 32*i);
        float v[8];
        #pragma unroll
        for (int j = 0; j < 8; j++) {
            int g = gbase + tc*8 + j;
            float bias = (m == 0) ? __ldg(&Fb[g]) : (m == 1 ? __ldg(&Gb[g]) : 0.f);
            v[j] = acc[i][j] + bias;
            if (m == 0) v[j] = fmaxf(v[j], 0.f);
        }
        if (m == 1) {
            float* outp = aside ? (g_aG1 + (size_t)b_*NS*ND) : g_bg1;
            float4* o4 = (float4*)(outp + (size_t)row*ND + gbase + tc*8);
            o4[0] = make_float4(v[0],v[1],v[2],v[3]);
            o4[1] = make_float4(v[4],v[5],v[6],v[7]);
        } else {
            bf16* outp = (m == 0)
                ? (aside ? (g_am + (size_t)b_*NS*ND) : g_bm)
                : g_bg2;   // m==2 b-side
            uint4* o4 = (uint4*)(outp + (size_t)row*ND + gbase + tc*8);
            *o4 = make_uint4(pkf(v[0],v[1]), pkf(v[2],v[3]),
                             pkf(v[4],v[5]), pkf(v[6],v[7]));
        }
    }
}

// =========================================================================
// Pair kernel: one CTA per (b,c). 512 threads / 16 warps. bf16 mma k16.
// =========================================================================
__global__ void __launch_bounds__(512) pair_kernel(
    const int*   __restrict__ cand,
    const float* __restrict__ HW,
    const float* __restrict__ Hb,
    float*       __restrict__ out)
{
    extern __shared__ char smc[];
    bf16*  s_am   = (bf16*) (smc + OB_AM);     // [128][264]
    bf16*  s_bm   = (bf16*) (smc + OB_BM);     // [64][264]
    bf16*  s_bg2t = (bf16*) (smc + OB_BG2T);   // [256][72]
    bf16*  s_stg7 = (bf16*) (smc + OB_STG7);   // [256][136]
    float* s_e    = (float*)(smc + OB_E);      // [128][68]
    bf16*  s_beta = (bf16*) (smc + OB_BETA);   // [128][72]
    bf16*  s_alpt = (bf16*) (smc + OB_ALPT);   // [64][136]
    int*   s_cid  = (int*)  (smc + OB_CID);
    float* sHW    = (float*)(smc + OB_HW);
    float* sRed   = (float*)(smc + OB_RED);

    const int tid  = threadIdx.x;
    const int p    = blockIdx.x;
    const int b    = p >> 6;
    const int w    = tid >> 5;
    const int lane = tid & 31;
    const int r    = lane >> 2;
    const int c    = lane & 3;

    if (tid < 256) { sHW[tid] = __ldg(&HW[tid]); sHW[tid+256] = __ldg(&HW[tid+256]); }
    if (tid < 64)  s_cid[tid] = __ldg(&cand[p*NZ + tid]);

    // ---- P1: stage a_m (full 128x256) + gather b_m rows ----
    {
        const uint4* src = (const uint4*)(g_am + (size_t)b*NS*ND);
        #pragma unroll
        for (int t = 0; t < 8; t++) {
            int idx = tid + 512*t;
            int row = idx >> 5, c8 = (idx & 31) * 8;
            *(uint4*)(s_am + row*P_AM + c8) = __ldg(&src[idx]);
        }
        #pragma unroll
        for (int t = 0; t < 4; t++) {
            int idx = tid + 512*t;
            int z = idx >> 5, c8 = (idx & 31) * 8;
            int id = __ldg(&cand[p*NZ + z]);
            *(uint4*)(s_bm + z*P_BM + c8) = __ldg((const uint4*)(g_bm + (size_t)id*ND + c8));
        }
    }
    __syncthreads();

    // ---- P3: e[s][z] = a_m @ b_m^T ----
    {
        const int wm = w >> 1;
        const int wn = w & 1;
        const int s0 = wm*16, zb = wn*32;
        float acc[4][4];
        #pragma unroll
        for (int f=0;f<4;f++){ acc[f][0]=0.f;acc[f][1]=0.f;acc[f][2]=0.f;acc[f][3]=0.f; }

        const bf16* ap0 = s_am + (s0 + r)*P_AM + 2*c;
        #pragma unroll 4
        for (int ks = 0; ks < 16; ks++) {
            const bf16* ap = ap0 + ks*16;
            uint32_t a0 = ldb(ap), a1 = ldb(ap + 8*P_AM), a2 = ldb(ap + 8), a3 = ldb(ap + 8*P_AM + 8);
            #pragma unroll
            for (int f = 0; f < 4; f++) {
                const bf16* bp = s_bm + (zb + f*8 + r)*P_BM + ks*16 + 2*c;
                mmab(acc[f], a0,a1,a2,a3, ldb(bp), ldb(bp+8));
            }
        }
        #pragma unroll
        for (int f = 0; f < 4; f++) {
            int col0 = zb + f*8 + 2*c;
            *(float2*)(s_e + (s0+r)*P_E + col0)   = make_float2(acc[f][0], acc[f][1]);
            *(float2*)(s_e + (s0+r+8)*P_E + col0) = make_float2(acc[f][2], acc[f][3]);
        }
    }
    __syncthreads();

    // ---- P4a: beta = softmax over z (rows) ----
    {
        #pragma unroll
        for (int rr = 0; rr < 8; rr++) {
            int s = w*8 + rr;
            float v0 = s_e[s*P_E + lane];
            float v1 = s_e[s*P_E + lane + 32];
            float mx = fmaxf(v0, v1);
            #pragma unroll
            for (int off = 16; off >= 1; off >>= 1)
                mx = fmaxf(mx, __shfl_xor_sync(0xffffffffu, mx, off));
            float e0 = expf(v0 - mx), e1 = expf(v1 - mx);
            float ss = e0 + e1;
            #pragma unroll
            for (int off = 16; off >= 1; off >>= 1)
                ss += __shfl_xor_sync(0xffffffffu, ss, off);
            float inv = 1.f / ss;
            s_beta[s*P_BETA + lane]      = __float2bfloat16_rn(e0 * inv);
            s_beta[s*P_BETA + lane + 32] = __float2bfloat16_rn(e1 * inv);
        }
    }

    // ---- P4b: alpha = softmax over s (cols) -> s_alpt transposed ----
    {
        const int z = tid >> 3, q = tid & 7;
        float ev[16];
        float mx = -1e30f;
        #pragma unroll
        for (int i = 0; i < 16; i++) {
            ev[i] = s_e[(q*16 + i)*P_E + z];
            mx = fmaxf(mx, ev[i]);
        }
        mx = fmaxf(mx, __shfl_xor_sync(0xffffffffu, mx, 1));
        mx = fmaxf(mx, __shfl_xor_sync(0xffffffffu, mx, 2));
        mx = fmaxf(mx, __shfl_xor_sync(0xffffffffu, mx, 4));
        float ss = 0.f;
        #pragma unroll
        for (int i = 0; i < 16; i++) { ev[i] = expf(ev[i] - mx); ss += ev[i]; }
        ss += __shfl_xor_sync(0xffffffffu, ss, 1);
        ss += __shfl_xor_sync(0xffffffffu, ss, 2);
        ss += __shfl_xor_sync(0xffffffffu, ss, 4);
        float inv = 1.f / ss;
        #pragma unroll
        for (int i = 0; i < 8; i++) {
            uint32_t u = pkf(ev[2*i]*inv, ev[2*i+1]*inv);
            *(uint32_t*)(s_alpt + z*P_ALPT + q*16 + 2*i) = u;
        }
    }

    // ---- gather bbG2^T + stage aG2^T ----
    {
        const int half = tid >> 8;
        const int g    = tid & 255;
        #pragma unroll
        for (int t = 0; t < 16; t++) {
            int z0 = (half*16 + t) * 2;
            int id0 = s_cid[z0], id1 = s_cid[z0+1];
            bf16 v0 = __ldg(g_bg2 + (size_t)id0*ND + g);
            bf16 v1 = __ldg(g_bg2 + (size_t)id1*ND + g);
            *(uint32_t*)(s_bg2t + g*P_BG2T + z0) = pkh(v0, v1);
        }
        const uint4* src = (const uint4*)(g_aG2T + (size_t)b*ND*NS);
        #pragma unroll
        for (int t = 0; t < 8; t++) {
            int idx = tid + 512*t;
            int gg = idx >> 4, c8 = (idx & 15) * 8;
            *(uint4*)(s_stg7 + gg*P_STG7 + c8) = __ldg(&src[idx]);
        }
    }
    __syncthreads();

    float y_local = 0.f;

    // ---- P6: y1 += sum relu(aG1 + beta @ bbG2) * HW1 ----
    {
        const int wm = w >> 2;
        const int wn = w & 3;
        const float* aG1p = g_aG1 + (size_t)b*NS*ND;
        float acc[2][8][4];
        #pragma unroll
        for (int mi=0;mi<2;mi++)
            #pragma unroll
            for (int f=0;f<8;f++)
                #pragma unroll
                for (int e=0;e<4;e++) acc[mi][f][e]=0.f;
        #pragma unroll
        for (int kz = 0; kz < 4; kz++) {
            uint32_t afr[2][4];
            #pragma unroll
            for (int mi = 0; mi < 2; mi++) {
                const bf16* ap = s_beta + (wm*32 + mi*16 + r)*P_BETA + kz*16 + 2*c;
                afr[mi][0]=ldb(ap); afr[mi][1]=ldb(ap+8*P_BETA);
                afr[mi][2]=ldb(ap+8); afr[mi][3]=ldb(ap+8*P_BETA+8);
            }
            #pragma unroll
            for (int f = 0; f < 8; f++) {
                const bf16* bp = s_bg2t + (wn*64 + f*8 + r)*P_BG2T + kz*16 + 2*c;
                uint32_t b0 = ldb(bp), b1 = ldb(bp+8);
                mmab(acc[0][f], afr[0][0],afr[0][1],afr[0][2],afr[0][3], b0,b1);
                mmab(acc[1][f], afr[1][0],afr[1][1],afr[1][2],afr[1][3], b0,b1);
            }
        }
        #pragma unroll
        for (int mi=0;mi<2;mi++)
            #pragma unroll
            for (int f=0;f<8;f++){
                int row0 = wm*32 + mi*16 + r;
                int col0 = wn*64 + f*8 + 2*c;
                float2 g0 = __ldg((const float2*)(aG1p + (size_t)row0*ND + col0));
                float2 g1 = __ldg((const float2*)(aG1p + (size_t)(row0+8)*ND + col0));
                float h0 = sHW[col0], h1 = sHW[col0+1];
                y_local += fmaxf(acc[mi][f][0] + g0.x, 0.f)*h0
                         + fmaxf(acc[mi][f][1] + g0.y, 0.f)*h1
                         + fmaxf(acc[mi][f][2] + g1.x, 0.f)*h0
                         + fmaxf(acc[mi][f][3] + g1.y, 0.f)*h1;
            }
    }

    // ---- P7: y2 += sum relu(bG1 + alpha^T @ aG2) * HW2 ----
    {
        const int wm = w >> 3;
        const int wn = w & 7;
        float acc[2][4][4];
        #pragma unroll
        for (int mi=0;mi<2;mi++)
            #pragma unroll
            for (int f=0;f<4;f++){
                int row0 = wm*32 + mi*16 + r;
                int col0 = wn*32 + f*8 + 2*c;
                int id0 = s_cid[row0], id1 = s_cid[row0+8];
                float2 u0 = __ldg((const float2*)(g_bg1 + (size_t)id0*ND + col0));
                float2 u1 = __ldg((const float2*)(g_bg1 + (size_t)id1*ND + col0));
                acc[mi][f][0]=u0.x; acc[mi][f][1]=u0.y;
                acc[mi][f][2]=u1.x; acc[mi][f][3]=u1.y;
            }
        #pragma unroll
        for (int ks = 0; ks < 8; ks++) {
            uint32_t afr[2][4];
            #pragma unroll
            for (int mi = 0; mi < 2; mi++) {
                const bf16* ap = s_alpt + (wm*32 + mi*16 + r)*P_ALPT + ks*16 + 2*c;
                afr[mi][0]=ldb(ap); afr[mi][1]=ldb(ap+8*P_ALPT);
                afr[mi][2]=ldb(ap+8); afr[mi][3]=ldb(ap+8*P_ALPT+8);
            }
            #pragma unroll
            for (int f = 0; f < 4; f++) {
                const bf16* bp = s_stg7 + (wn*32 + f*8 + r)*P_STG7 + ks*16 + 2*c;
                uint32_t b0 = ldb(bp), b1 = ldb(bp+8);
                mmab(acc[0][f], afr[0][0],afr[0][1],afr[0][2],afr[0][3], b0,b1);
                mmab(acc[1][f], afr[1][0],afr[1][1],afr[1][2],afr[1][3], b0,b1);
            }
        }
        #pragma unroll
        for (int mi=0;mi<2;mi++)
            #pragma unroll
            for (int f=0;f<4;f++){
                int col0 = wn*32 + f*8 + 2*c;
                float h0 = sHW[256+col0], h1 = sHW[256+col0+1];
                y_local += fmaxf(acc[mi][f][0], 0.f)*h0
                         + fmaxf(acc[mi][f][1], 0.f)*h1
                         + fmaxf(acc[mi][f][2], 0.f)*h0
                         + fmaxf(acc[mi][f][3], 0.f)*h1;
            }
    }
    __syncthreads();

    // ---- block reduce ----
    {
        #pragma unroll
        for (int off = 16; off >= 1; off >>= 1)
            y_local += __shfl_xor_sync(0xffffffffu, y_local, off);
        if (lane == 0) sRed[w] = y_local;
        __syncthreads();
        if (tid == 0) {
            float t = 0.f;
            #pragma unroll
            for (int ww = 0; ww < 16; ww++) t += sRed[ww];
            out[p] = t + __ldg(&Hb[0]);
        }
    }
}

// =========================================================================
extern "C" void kernel_launch(void* const* d_in, const int* in_sizes, int n_in,
                              void* d_out, int out_size)
{
    const int*   inptensor = (const int*)  d_in[0];
    const int*   cand      = (const int*)  d_in[1];
    const float* EmbA      = (const float*)d_in[4];
    const float* EmbB      = (const float*)d_in[5];
    const float* FW        = (const float*)d_in[6];
    const float* Fb        = (const float*)d_in[7];
    const float* GW        = (const float*)d_in[8];
    const float* Gb        = (const float*)d_in[9];
    const float* HW        = (const float*)d_in[10];
    const float* Hb        = (const float*)d_in[11];
    float*       out       = (float*)d_out;

    (void)in_sizes; (void)n_in; (void)out_size;

    const int smem1 = (64*257 + 16*64) * 4;    // 69888 B -> 2 CTAs/SM
    cudaFuncSetAttribute(tables_kernel, cudaFuncAttributeMaxDynamicSharedMemorySize, smem1);
    cudaFuncSetAttribute(pair_kernel,   cudaFuncAttributeMaxDynamicSharedMemorySize, SMEM_PAIR);

    tables_kernel<<<dim3(12, 2*NB + VOP/64), 256, smem1>>>(
        inptensor, EmbA, EmbB, FW, Fb, GW, Gb);
    pair_kernel<<<NB*NC, 512, SMEM_PAIR>>>(cand, HW, Hb, out);
}

// round 10
// speedup vs baseline: 1.6335x; 1.6335x over previous
#include <cuda_runtime.h>
#include <cuda_bf16.h>
#include <cstdint>

#define NB 32
#define NC 64
#define NS 128
#define NZ 64
#define ND 256
#define VO 5000
#define VOP 5120

typedef __nv_bfloat16 bf16;

// ---- pair-kernel smem byte offsets ----
#define OB_AM    0
#define OB_BM    67584
#define OB_BG2T  0
#define OB_STG7  36864
#define OB_E     106496
#define OB_BETA  141312
#define OB_ALPT  159744
#define OB_CID   177152
#define OB_HW    177408
#define OB_RED   179456
#define SMEM_PAIR 179520

// pitches (elements)
#define P_AM   264
#define P_BM   264
#define P_E    68
#define P_BETA 72
#define P_BG2T 72
#define P_ALPT 136
#define P_STG7 136

// tables kernel smem (floats)
#define TA_PITCH 260            // a_tile [64][260] fp32 (tf32-rounded)
#define TW_PITCH 264            // wst [16][264]
#define T_WST_OFF (64*TA_PITCH) // 16640
#define T_SMEM_FL (64*TA_PITCH + 16*TW_PITCH)   // 20864 floats = 83456 B

// ---------------- device scratch ----------------
__device__ bf16  g_am  [NB*NS*ND];
__device__ float g_aG1 [NB*NS*ND];
__device__ bf16  g_aG2T[NB*ND*NS];
__device__ bf16  g_bm  [VOP*ND];
__device__ float g_bg1 [VOP*ND];
__device__ bf16  g_bg2 [VOP*ND];

// ---------------- helpers ----------------
__device__ __forceinline__ uint32_t f2t(float f){
    uint32_t u; asm("cvt.rna.tf32.f32 %0, %1;" : "=r"(u) : "f"(f)); return u;
}
__device__ __forceinline__ float rtf(float f){ return __uint_as_float(f2t(f)); }
__device__ __forceinline__ uint32_t ldu(const float* p){ return __float_as_uint(*p); }
__device__ __forceinline__ uint32_t ldb(const bf16* p){
    return *reinterpret_cast<const uint32_t*>(p);
}
__device__ __forceinline__ uint32_t pkf(float a, float b){
    __nv_bfloat162 t = __floats2bfloat162_rn(a, b);
    return *reinterpret_cast<uint32_t*>(&t);
}
__device__ __forceinline__ uint32_t pkh(bf16 a, bf16 b){
    __nv_bfloat162 t = __halves2bfloat162(a, b);
    return *reinterpret_cast<uint32_t*>(&t);
}
// tf32 m16n8k8: a0=(r,c) a1=(r+8,c) a2=(r,c+4) a3=(r+8,c+4)
__device__ __forceinline__ void mma8(float* d,
    uint32_t a0,uint32_t a1,uint32_t a2,uint32_t a3, uint32_t b0,uint32_t b1){
    asm volatile("mma.sync.aligned.m16n8k8.row.col.f32.tf32.tf32.f32 "
        "{%0,%1,%2,%3}, {%4,%5,%6,%7}, {%8,%9}, {%0,%1,%2,%3};\n"
        : "+f"(d[0]),"+f"(d[1]),"+f"(d[2]),"+f"(d[3])
        : "r"(a0),"r"(a1),"r"(a2),"r"(a3),"r"(b0),"r"(b1));
}
// bf16 m16n8k16
__device__ __forceinline__ void mmab(float* d,
    uint32_t a0,uint32_t a1,uint32_t a2,uint32_t a3, uint32_t b0,uint32_t b1){
    asm volatile("mma.sync.aligned.m16n8k16.row.col.f32.bf16.bf16.f32 "
        "{%0,%1,%2,%3}, {%4,%5,%6,%7}, {%8,%9}, {%0,%1,%2,%3};\n"
        : "+f"(d[0]),"+f"(d[1]),"+f"(d[2]),"+f"(d[3])
        : "r"(a0),"r"(a1),"r"(a2),"r"(a3),"r"(b0),"r"(b1));
}

// =========================================================================
// Tables kernel v2: tf32 mma.sync GEMM. 64 rows x 64 cols per CTA, K=256.
// grid=(12, 144): y<64 -> a-side (b=y>>1, half=y&1); else vocab tile rt=y-64.
// m = chunk>>2: 0 F+relu, 1 GW1+Gb (fp32 out), 2 GW2 (a-side -> g_aG2T transposed)
// 8 warps: wm=w>>1 (m16 tile of 4), wn=w&1 (n32 block, 4 n8 tiles).
// =========================================================================
__global__ void __launch_bounds__(256) tables_kernel(
    const int*   __restrict__ inptensor,
    const float* __restrict__ EmbA,
    const float* __restrict__ EmbB,
    const float* __restrict__ FW,
    const float* __restrict__ Fb,
    const float* __restrict__ GW,
    const float* __restrict__ Gb)
{
    extern __shared__ float sm[];
    float* a_tile = sm;               // [64][260] tf32-rounded
    float* wst    = sm + T_WST_OFF;   // [16][264] tf32-rounded

    const int y     = blockIdx.y;
    const int chunk = blockIdx.x;
    const int m     = chunk >> 2;
    const int gbase = (chunk & 3) * 64;
    const int tid   = threadIdx.x;
    const bool aside = (y < 2*NB);
    const int w    = tid >> 5;
    const int lane = tid & 31;
    const int r    = lane >> 2;
    const int c    = lane & 3;
    const int wm   = w >> 1;          // 0..3
    const int wn   = w & 1;           // 0..1

    // ---- gather rows (tf32-rounded at store) ----
    if (aside) {
        const int b = y >> 1, sh = (y & 1) * 64;
        for (int s = 0; s < 64; s++) {
            int idx = __ldg(&inptensor[b*NS + sh + s]);
            a_tile[s*TA_PITCH + tid] = rtf(__ldg(&EmbA[(size_t)idx*ND + tid]));
        }
    } else {
        const int rt = y - 2*NB;
        for (int s = 0; s < 64; s++) {
            int row = rt*64 + s;
            int rr = (row < VO) ? row : 0;
            a_tile[s*TA_PITCH + tid] = rtf(__ldg(&EmbB[(size_t)rr*ND + tid]));
        }
    }
    __syncthreads();

    const float* Wsrc = (m == 0) ? FW : GW;
    const int wrow_off = (m == 2) ? 256 : 0;

    float acc[4][4];
    #pragma unroll
    for (int f = 0; f < 4; f++)
        #pragma unroll
        for (int e = 0; e < 4; e++) acc[f][e] = 0.f;

    for (int t = 0; t < 16; t++) {
        int k0 = t*16;
        #pragma unroll
        for (int q = 0; q < 4; q++) {
            int idx2 = tid + 256*q;
            int kk = idx2 >> 6, gg = idx2 & 63;
            wst[kk*TW_PITCH + gg] =
                rtf(__ldg(&Wsrc[(size_t)(k0 + kk + wrow_off)*256 + gbase + gg]));
        }
        __syncthreads();
        #pragma unroll
        for (int kh = 0; kh < 2; kh++) {
            const float* ap = a_tile + (wm*16 + r)*TA_PITCH + k0 + kh*8 + c;
            uint32_t a0 = ldu(ap), a1 = ldu(ap + 8*TA_PITCH);
            uint32_t a2 = ldu(ap + 4), a3 = ldu(ap + 8*TA_PITCH + 4);
            #pragma unroll
            for (int f = 0; f < 4; f++) {
                const float* bp = wst + (kh*8 + c)*TW_PITCH + wn*32 + f*8 + r;
                mma8(acc[f], a0,a1,a2,a3, ldu(bp), ldu(bp + 4*TW_PITCH));
            }
        }
        __syncthreads();
    }

    const int b_ = y >> 1, sh = (y & 1) * 64;
    const int rt = y - 2*NB;
    const int lr0 = wm*16 + r;          // local row (0..63), +8 sibling

    if (m == 2 && aside) {
        // transpose via smem (a_tile dead), coalesced store to g_aG2T [b][g][s]
        bf16* tbuf = (bf16*)a_tile;     // [64 g][66 s]
        #pragma unroll
        for (int f = 0; f < 4; f++) {
            int lc = wn*32 + f*8 + c*2;
            tbuf[lc*66 + lr0]       = __float2bfloat16_rn(acc[f][0]);
            tbuf[(lc+1)*66 + lr0]   = __float2bfloat16_rn(acc[f][1]);
            tbuf[lc*66 + lr0+8]     = __float2bfloat16_rn(acc[f][2]);
            tbuf[(lc+1)*66 + lr0+8] = __float2bfloat16_rn(acc[f][3]);
        }
        __syncthreads();
        int gl = tid >> 2;
        int sc = (tid & 3) * 16;
        const uint32_t* src = (const uint32_t*)(tbuf + gl*66 + sc);
        uint32_t v0=src[0],v1=src[1],v2=src[2],v3=src[3];
        uint32_t v4=src[4],v5=src[5],v6=src[6],v7=src[7];
        uint4* dst = (uint4*)(g_aG2T + ((size_t)b_*ND + gbase + gl)*NS + sh + sc);
        dst[0] = make_uint4(v0,v1,v2,v3);
        dst[1] = make_uint4(v4,v5,v6,v7);
        return;
    }

    // generic epilogue: bias (+relu) and store per fragment
    #pragma unroll
    for (int f = 0; f < 4; f++) {
        int col = gbase + wn*32 + f*8 + c*2;
        float b0 = (m == 0) ? __ldg(&Fb[col])   : (m == 1 ? __ldg(&Gb[col])   : 0.f);
        float b1 = (m == 0) ? __ldg(&Fb[col+1]) : (m == 1 ? __ldg(&Gb[col+1]) : 0.f);
        float v00 = acc[f][0] + b0, v01 = acc[f][1] + b1;
        float v10 = acc[f][2] + b0, v11 = acc[f][3] + b1;
        if (m == 0) {
            v00 = fmaxf(v00, 0.f); v01 = fmaxf(v01, 0.f);
            v10 = fmaxf(v10, 0.f); v11 = fmaxf(v11, 0.f);
        }
        int row0 = aside ? (sh + lr0) : (rt*64 + lr0);
        int row1 = row0 + 8;
        if (m == 1) {
            float* outp = aside ? (g_aG1 + (size_t)b_*NS*ND) : g_bg1;
            *(float2*)(outp + (size_t)row0*ND + col) = make_float2(v00, v01);
            *(float2*)(outp + (size_t)row1*ND + col) = make_float2(v10, v11);
        } else {
            bf16* outp = (m == 0) ? (aside ? (g_am + (size_t)b_*NS*ND) : g_bm)
                                  : g_bg2;
            *(uint32_t*)(outp + (size_t)row0*ND + col) = pkf(v00, v01);
            *(uint32_t*)(outp + (size_t)row1*ND + col) = pkf(v10, v11);
        }
    }
}

// =========================================================================
// Pair kernel: one CTA per (b,c). 512 threads / 16 warps. bf16 mma k16.
// (unchanged from R8 — 223.8 us, rel_err 4.0e-4)
// =========================================================================
__global__ void __launch_bounds__(512) pair_kernel(
    const int*   __restrict__ cand,
    const float* __restrict__ HW,
    const float* __restrict__ Hb,
    float*       __restrict__ out)
{
    extern __shared__ char smc[];
    bf16*  s_am   = (bf16*) (smc + OB_AM);
    bf16*  s_bm   = (bf16*) (smc + OB_BM);
    bf16*  s_bg2t = (bf16*) (smc + OB_BG2T);
    bf16*  s_stg7 = (bf16*) (smc + OB_STG7);
    float* s_e    = (float*)(smc + OB_E);
    bf16*  s_beta = (bf16*) (smc + OB_BETA);
    bf16*  s_alpt = (bf16*) (smc + OB_ALPT);
    int*   s_cid  = (int*)  (smc + OB_CID);
    float* sHW    = (float*)(smc + OB_HW);
    float* sRed   = (float*)(smc + OB_RED);

    const int tid  = threadIdx.x;
    const int p    = blockIdx.x;
    const int b    = p >> 6;
    const int w    = tid >> 5;
    const int lane = tid & 31;
    const int r    = lane >> 2;
    const int c    = lane & 3;

    if (tid < 256) { sHW[tid] = __ldg(&HW[tid]); sHW[tid+256] = __ldg(&HW[tid+256]); }
    if (tid < 64)  s_cid[tid] = __ldg(&cand[p*NZ + tid]);

    // ---- P1: stage a_m + gather b_m ----
    {
        const uint4* src = (const uint4*)(g_am + (size_t)b*NS*ND);
        #pragma unroll
        for (int t = 0; t < 8; t++) {
            int idx = tid + 512*t;
            int row = idx >> 5, c8 = (idx & 31) * 8;
            *(uint4*)(s_am + row*P_AM + c8) = __ldg(&src[idx]);
        }
        #pragma unroll
        for (int t = 0; t < 4; t++) {
            int idx = tid + 512*t;
            int z = idx >> 5, c8 = (idx & 31) * 8;
            int id = __ldg(&cand[p*NZ + z]);
            *(uint4*)(s_bm + z*P_BM + c8) = __ldg((const uint4*)(g_bm + (size_t)id*ND + c8));
        }
    }
    __syncthreads();

    // ---- P3: e = a_m @ b_m^T ----
    {
        const int wm = w >> 1;
        const int wn = w & 1;
        const int s0 = wm*16, zb = wn*32;
        float acc[4][4];
        #pragma unroll
        for (int f=0;f<4;f++){ acc[f][0]=0.f;acc[f][1]=0.f;acc[f][2]=0.f;acc[f][3]=0.f; }

        const bf16* ap0 = s_am + (s0 + r)*P_AM + 2*c;
        #pragma unroll 4
        for (int ks = 0; ks < 16; ks++) {
            const bf16* ap = ap0 + ks*16;
            uint32_t a0 = ldb(ap), a1 = ldb(ap + 8*P_AM), a2 = ldb(ap + 8), a3 = ldb(ap + 8*P_AM + 8);
            #pragma unroll
            for (int f = 0; f < 4; f++) {
                const bf16* bp = s_bm + (zb + f*8 + r)*P_BM + ks*16 + 2*c;
                mmab(acc[f], a0,a1,a2,a3, ldb(bp), ldb(bp+8));
            }
        }
        #pragma unroll
        for (int f = 0; f < 4; f++) {
            int col0 = zb + f*8 + 2*c;
            *(float2*)(s_e + (s0+r)*P_E + col0)   = make_float2(acc[f][0], acc[f][1]);
            *(float2*)(s_e + (s0+r+8)*P_E + col0) = make_float2(acc[f][2], acc[f][3]);
        }
    }
    __syncthreads();

    // ---- P4a: beta softmax (rows) ----
    {
        #pragma unroll
        for (int rr = 0; rr < 8; rr++) {
            int s = w*8 + rr;
            float v0 = s_e[s*P_E + lane];
            float v1 = s_e[s*P_E + lane + 32];
            float mx = fmaxf(v0, v1);
            #pragma unroll
            for (int off = 16; off >= 1; off >>= 1)
                mx = fmaxf(mx, __shfl_xor_sync(0xffffffffu, mx, off));
            float e0 = expf(v0 - mx), e1 = expf(v1 - mx);
            float ss = e0 + e1;
            #pragma unroll
            for (int off = 16; off >= 1; off >>= 1)
                ss += __shfl_xor_sync(0xffffffffu, ss, off);
            float inv = 1.f / ss;
            s_beta[s*P_BETA + lane]      = __float2bfloat16_rn(e0 * inv);
            s_beta[s*P_BETA + lane + 32] = __float2bfloat16_rn(e1 * inv);
        }
    }

    // ---- P4b: alpha softmax (cols) -> s_alpt transposed ----
    {
        const int z = tid >> 3, q = tid & 7;
        float ev[16];
        float mx = -1e30f;
        #pragma unroll
        for (int i = 0; i < 16; i++) {
            ev[i] = s_e[(q*16 + i)*P_E + z];
            mx = fmaxf(mx, ev[i]);
        }
        mx = fmaxf(mx, __shfl_xor_sync(0xffffffffu, mx, 1));
        mx = fmaxf(mx, __shfl_xor_sync(0xffffffffu, mx, 2));
        mx = fmaxf(mx, __shfl_xor_sync(0xffffffffu, mx, 4));
        float ss = 0.f;
        #pragma unroll
        for (int i = 0; i < 16; i++) { ev[i] = expf(ev[i] - mx); ss += ev[i]; }
        ss += __shfl_xor_sync(0xffffffffu, ss, 1);
        ss += __shfl_xor_sync(0xffffffffu, ss, 2);
        ss += __shfl_xor_sync(0xffffffffu, ss, 4);
        float inv = 1.f / ss;
        #pragma unroll
        for (int i = 0; i < 8; i++) {
            uint32_t u = pkf(ev[2*i]*inv, ev[2*i+1]*inv);
            *(uint32_t*)(s_alpt + z*P_ALPT + q*16 + 2*i) = u;
        }
    }

    // ---- gather bbG2^T + stage aG2^T ----
    {
        const int half = tid >> 8;
        const int g    = tid & 255;
        #pragma unroll
        for (int t = 0; t < 16; t++) {
            int z0 = (half*16 + t) * 2;
            int id0 = s_cid[z0], id1 = s_cid[z0+1];
            bf16 v0 = __ldg(g_bg2 + (size_t)id0*ND + g);
            bf16 v1 = __ldg(g_bg2 + (size_t)id1*ND + g);
            *(uint32_t*)(s_bg2t + g*P_BG2T + z0) = pkh(v0, v1);
        }
        const uint4* src = (const uint4*)(g_aG2T + (size_t)b*ND*NS);
        #pragma unroll
        for (int t = 0; t < 8; t++) {
            int idx = tid + 512*t;
            int gg = idx >> 4, c8 = (idx & 15) * 8;
            *(uint4*)(s_stg7 + gg*P_STG7 + c8) = __ldg(&src[idx]);
        }
    }
    __syncthreads();

    float y_local = 0.f;

    // ---- P6 ----
    {
        const int wm = w >> 2;
        const int wn = w & 3;
        const float* aG1p = g_aG1 + (size_t)b*NS*ND;
        float acc[2][8][4];
        #pragma unroll
        for (int mi=0;mi<2;mi++)
            #pragma unroll
            for (int f=0;f<8;f++)
                #pragma unroll
                for (int e=0;e<4;e++) acc[mi][f][e]=0.f;
        #pragma unroll
        for (int kz = 0; kz < 4; kz++) {
            uint32_t afr[2][4];
            #pragma unroll
            for (int mi = 0; mi < 2; mi++) {
                const bf16* ap = s_beta + (wm*32 + mi*16 + r)*P_BETA + kz*16 + 2*c;
                afr[mi][0]=ldb(ap); afr[mi][1]=ldb(ap+8*P_BETA);
                afr[mi][2]=ldb(ap+8); afr[mi][3]=ldb(ap+8*P_BETA+8);
            }
            #pragma unroll
            for (int f = 0; f < 8; f++) {
                const bf16* bp = s_bg2t + (wn*64 + f*8 + r)*P_BG2T + kz*16 + 2*c;
                uint32_t b0 = ldb(bp), b1 = ldb(bp+8);
                mmab(acc[0][f], afr[0][0],afr[0][1],afr[0][2],afr[0][3], b0,b1);
                mmab(acc[1][f], afr[1][0],afr[1][1],afr[1][2],afr[1][3], b0,b1);
            }
        }
        #pragma unroll
        for (int mi=0;mi<2;mi++)
            #pragma unroll
            for (int f=0;f<8;f++){
                int row0 = wm*32 + mi*16 + r;
                int col0 = wn*64 + f*8 + 2*c;
                float2 g0 = __ldg((const float2*)(aG1p + (size_t)row0*ND + col0));
                float2 g1 = __ldg((const float2*)(aG1p + (size_t)(row0+8)*ND + col0));
                float h0 = sHW[col0], h1 = sHW[col0+1];
                y_local += fmaxf(acc[mi][f][0] + g0.x, 0.f)*h0
                         + fmaxf(acc[mi][f][1] + g0.y, 0.f)*h1
                         + fmaxf(acc[mi][f][2] + g1.x, 0.f)*h0
                         + fmaxf(acc[mi][f][3] + g1.y, 0.f)*h1;
            }
    }

    // ---- P7 ----
    {
        const int wm = w >> 3;
        const int wn = w & 7;
        float acc[2][4][4];
        #pragma unroll
        for (int mi=0;mi<2;mi++)
            #pragma unroll
            for (int f=0;f<4;f++){
                int row0 = wm*32 + mi*16 + r;
                int col0 = wn*32 + f*8 + 2*c;
                int id0 = s_cid[row0], id1 = s_cid[row0+8];
                float2 u0 = __ldg((const float2*)(g_bg1 + (size_t)id0*ND + col0));
                float2 u1 = __ldg((const float2*)(g_bg1 + (size_t)id1*ND + col0));
                acc[mi][f][0]=u0.x; acc[mi][f][1]=u0.y;
                acc[mi][f][2]=u1.x; acc[mi][f][3]=u1.y;
            }
        #pragma unroll
        for (int ks = 0; ks < 8; ks++) {
            uint32_t afr[2][4];
            #pragma unroll
            for (int mi = 0; mi < 2; mi++) {
                const bf16* ap = s_alpt + (wm*32 + mi*16 + r)*P_ALPT + ks*16 + 2*c;
                afr[mi][0]=ldb(ap); afr[mi][1]=ldb(ap+8*P_ALPT);
                afr[mi][2]=ldb(ap+8); afr[mi][3]=ldb(ap+8*P_ALPT+8);
            }
            #pragma unroll
            for (int f = 0; f < 4; f++) {
                const bf16* bp = s_stg7 + (wn*32 + f*8 + r)*P_STG7 + ks*16 + 2*c;
                uint32_t b0 = ldb(bp), b1 = ldb(bp+8);
                mmab(acc[0][f], afr[0][0],afr[0][1],afr[0][2],afr[0][3], b0,b1);
                mmab(acc[1][f], afr[1][0],afr[1][1],afr[1][2],afr[1][3], b0,b1);
            }
        }
        #pragma unroll
        for (int mi=0;mi<2;mi++)
            #pragma unroll
            for (int f=0;f<4;f++){
                int col0 = wn*32 + f*8 + 2*c;
                float h0 = sHW[256+col0], h1 = sHW[256+col0+1];
                y_local += fmaxf(acc[mi][f][0], 0.f)*h0
                         + fmaxf(acc[mi][f][1], 0.f)*h1
                         + fmaxf(acc[mi][f][2], 0.f)*h0
                         + fmaxf(acc[mi][f][3], 0.f)*h1;
            }
    }
    __syncthreads();

    // ---- block reduce ----
    {
        #pragma unroll
        for (int off = 16; off >= 1; off >>= 1)
            y_local += __shfl_xor_sync(0xffffffffu, y_local, off);
        if (lane == 0) sRed[w] = y_local;
        __syncthreads();
        if (tid == 0) {
            float t = 0.f;
            #pragma unroll
            for (int ww = 0; ww < 16; ww++) t += sRed[ww];
            out[p] = t + __ldg(&Hb[0]);
        }
    }
}

// =========================================================================
extern "C" void kernel_launch(void* const* d_in, const int* in_sizes, int n_in,
                              void* d_out, int out_size)
{
    const int*   inptensor = (const int*)  d_in[0];
    const int*   cand      = (const int*)  d_in[1];
    const float* EmbA      = (const float*)d_in[4];
    const float* EmbB      = (const float*)d_in[5];
    const float* FW        = (const float*)d_in[6];
    const float* Fb        = (const float*)d_in[7];
    const float* GW        = (const float*)d_in[8];
    const float* Gb        = (const float*)d_in[9];
    const float* HW        = (const float*)d_in[10];
    const float* Hb        = (const float*)d_in[11];
    float*       out       = (float*)d_out;

    (void)in_sizes; (void)n_in; (void)out_size;

    const int smem1 = T_SMEM_FL * 4;           // 83456 B -> 2 CTAs/SM
    cudaFuncSetAttribute(tables_kernel, cudaFuncAttributeMaxDynamicSharedMemorySize, smem1);
    cudaFuncSetAttribute(pair_kernel,   cudaFuncAttributeMaxDynamicSharedMemorySize, SMEM_PAIR);

    tables_kernel<<<dim3(12, 2*NB + VOP/64), 256, smem1>>>(
        inptensor, EmbA, EmbB, FW, Fb, GW, Gb);
    pair_kernel<<<NB*NC, 512, SMEM_PAIR>>>(cand, HW, Hb, out);
}

// round 11
// speedup vs baseline: 1.7079x; 1.0455x over previous
#include <cuda_runtime.h>
#include <cuda_bf16.h>
#include <cstdint>

#define NB 32
#define NC 64
#define NS 128
#define NZ 64
#define ND 256
#define VO 5000
#define VOP 5120

typedef __nv_bfloat16 bf16;

// ---- pair-kernel smem byte offsets (total 108,864 B -> 2 CTAs/SM) ----
#define OB_BM    0         // b_m [64][264] bf16 = 33792           (phase 1-3)
#define OB_AMC   33792     // a_m chunks 2x[128][24] bf16 = 12288  (phase 3)
#define OB_BG2T  0         // bg2t [256][72] bf16 = 36864          (phase 5+, over bm)
#define OB_E     46080     // e bf16 [128][72] = 18432             (phase 3-4)
#define OB_ST7   46080     // st7 chunks 2x[256][24] bf16 = 24576  (phase 7, over e)
#define OB_BETA  70656     // beta bf16 [128][72] = 18432
#define OB_ALPT  89088     // alphaT bf16 [64][136] = 17408
#define OB_CID   106496    // 64 ints
#define OB_HW    106752    // 512 fp32
#define OB_RED   108800    // 8 fp32
#define SMEM_PAIR 108864

// pitches (bf16 elements)
#define P_BM   264
#define P_AMC  24
#define P_E    72
#define P_BETA 72
#define P_BG2T 72
#define P_ALPT 136
#define P_ST7  24

// tables kernel smem (floats)
#define TA_PITCH 260
#define TW_PITCH 264
#define T_WST_OFF (64*TA_PITCH)
#define T_SMEM_FL (64*TA_PITCH + 16*TW_PITCH)

// ---------------- device scratch ----------------
__device__ bf16  g_amC [NB*16*NS*16];  // a_m chunk-major [b][kc][s][16]
__device__ float g_aG1 [NB*NS*ND];     // exact a@GW1+Gb [b][s][g]
__device__ bf16  g_aG2C[NB*8*ND*16];   // (a@GW2)^T chunk-major [b][sc][g][16]
__device__ bf16  g_bm  [VOP*ND];       // relu(EmbB@FW+Fb) [v][k]
__device__ float g_bg1 [VOP*ND];       // exact EmbB@GW1+Gb [v][g]
__device__ bf16  g_bg2 [VOP*ND];       // EmbB@GW2 [v][g]

// ---------------- helpers ----------------
__device__ __forceinline__ uint32_t f2t(float f){
    uint32_t u; asm("cvt.rna.tf32.f32 %0, %1;" : "=r"(u) : "f"(f)); return u;
}
__device__ __forceinline__ float rtf(float f){ return __uint_as_float(f2t(f)); }
__device__ __forceinline__ uint32_t ldu(const float* p){ return __float_as_uint(*p); }
__device__ __forceinline__ uint32_t ldb(const bf16* p){
    return *reinterpret_cast<const uint32_t*>(p);
}
__device__ __forceinline__ uint32_t pkf(float a, float b){
    __nv_bfloat162 t = __floats2bfloat162_rn(a, b);
    return *reinterpret_cast<uint32_t*>(&t);
}
__device__ __forceinline__ uint32_t pkh(bf16 a, bf16 b){
    __nv_bfloat162 t = __halves2bfloat162(a, b);
    return *reinterpret_cast<uint32_t*>(&t);
}
__device__ __forceinline__ float b2f(bf16 v){ return __bfloat162float(v); }

// tf32 m16n8k8
__device__ __forceinline__ void mma8(float* d,
    uint32_t a0,uint32_t a1,uint32_t a2,uint32_t a3, uint32_t b0,uint32_t b1){
    asm volatile("mma.sync.aligned.m16n8k8.row.col.f32.tf32.tf32.f32 "
        "{%0,%1,%2,%3}, {%4,%5,%6,%7}, {%8,%9}, {%0,%1,%2,%3};\n"
        : "+f"(d[0]),"+f"(d[1]),"+f"(d[2]),"+f"(d[3])
        : "r"(a0),"r"(a1),"r"(a2),"r"(a3),"r"(b0),"r"(b1));
}
// bf16 m16n8k16
__device__ __forceinline__ void mmab(float* d,
    uint32_t a0,uint32_t a1,uint32_t a2,uint32_t a3, uint32_t b0,uint32_t b1){
    asm volatile("mma.sync.aligned.m16n8k16.row.col.f32.bf16.bf16.f32 "
        "{%0,%1,%2,%3}, {%4,%5,%6,%7}, {%8,%9}, {%0,%1,%2,%3};\n"
        : "+f"(d[0]),"+f"(d[1]),"+f"(d[2]),"+f"(d[3])
        : "r"(a0),"r"(a1),"r"(a2),"r"(a3),"r"(b0),"r"(b1));
}

// =========================================================================
// Tables kernel (tf32 mma). grid=(12, 144), 256 thr.
// y<64 -> a-side (b=y>>1, half=y&1); else vocab tile rt=y-64.
// m: 0 F+relu (a-side -> g_amC chunk-major; b-side -> g_bm),
//    1 GW1+Gb (fp32), 2 GW2 (a-side -> g_aG2C transposed chunk-major; b-side g_bg2)
// =========================================================================
__global__ void __launch_bounds__(256) tables_kernel(
    const int*   __restrict__ inptensor,
    const float* __restrict__ EmbA,
    const float* __restrict__ EmbB,
    const float* __restrict__ FW,
    const float* __restrict__ Fb,
    const float* __restrict__ GW,
    const float* __restrict__ Gb)
{
    extern __shared__ float sm[];
    float* a_tile = sm;               // [64][260] tf32-rounded
    float* wst    = sm + T_WST_OFF;   // [16][264]

    const int y     = blockIdx.y;
    const int chunk = blockIdx.x;
    const int m     = chunk >> 2;
    const int gbase = (chunk & 3) * 64;
    const int tid   = threadIdx.x;
    const bool aside = (y < 2*NB);
    const int w    = tid >> 5;
    const int lane = tid & 31;
    const int r    = lane >> 2;
    const int c    = lane & 3;
    const int wm   = w >> 1;
    const int wn   = w & 1;

    if (aside) {
        const int b = y >> 1, sh = (y & 1) * 64;
        for (int s = 0; s < 64; s++) {
            int idx = __ldg(&inptensor[b*NS + sh + s]);
            a_tile[s*TA_PITCH + tid] = rtf(__ldg(&EmbA[(size_t)idx*ND + tid]));
        }
    } else {
        const int rt = y - 2*NB;
        for (int s = 0; s < 64; s++) {
            int row = rt*64 + s;
            int rr = (row < VO) ? row : 0;
            a_tile[s*TA_PITCH + tid] = rtf(__ldg(&EmbB[(size_t)rr*ND + tid]));
        }
    }
    __syncthreads();

    const float* Wsrc = (m == 0) ? FW : GW;
    const int wrow_off = (m == 2) ? 256 : 0;

    float acc[4][4];
    #pragma unroll
    for (int f = 0; f < 4; f++)
        #pragma unroll
        for (int e = 0; e < 4; e++) acc[f][e] = 0.f;

    for (int t = 0; t < 16; t++) {
        int k0 = t*16;
        #pragma unroll
        for (int q = 0; q < 4; q++) {
            int idx2 = tid + 256*q;
            int kk = idx2 >> 6, gg = idx2 & 63;
            wst[kk*TW_PITCH + gg] =
                rtf(__ldg(&Wsrc[(size_t)(k0 + kk + wrow_off)*256 + gbase + gg]));
        }
        __syncthreads();
        #pragma unroll
        for (int kh = 0; kh < 2; kh++) {
            const float* ap = a_tile + (wm*16 + r)*TA_PITCH + k0 + kh*8 + c;
            uint32_t a0 = ldu(ap), a1 = ldu(ap + 8*TA_PITCH);
            uint32_t a2 = ldu(ap + 4), a3 = ldu(ap + 8*TA_PITCH + 4);
            #pragma unroll
            for (int f = 0; f < 4; f++) {
                const float* bp = wst + (kh*8 + c)*TW_PITCH + wn*32 + f*8 + r;
                mma8(acc[f], a0,a1,a2,a3, ldu(bp), ldu(bp + 4*TW_PITCH));
            }
        }
        __syncthreads();
    }

    const int b_ = y >> 1, sh = (y & 1) * 64;
    const int rt = y - 2*NB;
    const int lr0 = wm*16 + r;

    if (m == 2 && aside) {
        // transpose via smem, coalesced chunk-major store to g_aG2C [b][sc][g][16]
        bf16* tbuf = (bf16*)a_tile;     // [64 g][66 s]
        #pragma unroll
        for (int f = 0; f < 4; f++) {
            int lc = wn*32 + f*8 + c*2;
            tbuf[lc*66 + lr0]       = __float2bfloat16_rn(acc[f][0]);
            tbuf[(lc+1)*66 + lr0]   = __float2bfloat16_rn(acc[f][1]);
            tbuf[lc*66 + lr0+8]     = __float2bfloat16_rn(acc[f][2]);
            tbuf[(lc+1)*66 + lr0+8] = __float2bfloat16_rn(acc[f][3]);
        }
        __syncthreads();
        int gl = tid >> 2;
        int sc4 = tid & 3;
        int scG = (sh >> 4) + sc4;
        const uint32_t* src = (const uint32_t*)(tbuf + gl*66 + sc4*16);
        uint32_t v0=src[0],v1=src[1],v2=src[2],v3=src[3];
        uint32_t v4=src[4],v5=src[5],v6=src[6],v7=src[7];
        uint4* dst = (uint4*)(g_aG2C + (((size_t)b_*8 + scG)*ND + gbase + gl)*16);
        dst[0] = make_uint4(v0,v1,v2,v3);
        dst[1] = make_uint4(v4,v5,v6,v7);
        return;
    }

    #pragma unroll
    for (int f = 0; f < 4; f++) {
        int col = gbase + wn*32 + f*8 + c*2;
        float b0 = (m == 0) ? __ldg(&Fb[col])   : (m == 1 ? __ldg(&Gb[col])   : 0.f);
        float b1 = (m == 0) ? __ldg(&Fb[col+1]) : (m == 1 ? __ldg(&Gb[col+1]) : 0.f);
        float v00 = acc[f][0] + b0, v01 = acc[f][1] + b1;
        float v10 = acc[f][2] + b0, v11 = acc[f][3] + b1;
        if (m == 0) {
            v00 = fmaxf(v00, 0.f); v01 = fmaxf(v01, 0.f);
            v10 = fmaxf(v10, 0.f); v11 = fmaxf(v11, 0.f);
        }
        int row0 = aside ? (sh + lr0) : (rt*64 + lr0);
        int row1 = row0 + 8;
        if (m == 1) {
            float* outp = aside ? (g_aG1 + (size_t)b_*NS*ND) : g_bg1;
            *(float2*)(outp + (size_t)row0*ND + col) = make_float2(v00, v01);
            *(float2*)(outp + (size_t)row1*ND + col) = make_float2(v10, v11);
        } else if (m == 0 && aside) {
            // chunk-major g_amC [b][kc][s][16]
            int kc = col >> 4, kin = col & 15;
            bf16* base = g_amC + (((size_t)b_*16 + kc)*NS)*16 + kin;
            *(uint32_t*)(base + row0*16) = pkf(v00, v01);
            *(uint32_t*)(base + row1*16) = pkf(v10, v11);
        } else {
            bf16* outp = (m == 0) ? g_bm : g_bg2;
            *(uint32_t*)(outp + (size_t)row0*ND + col) = pkf(v00, v01);
            *(uint32_t*)(outp + (size_t)row1*ND + col) = pkf(v10, v11);
        }
    }
}

// =========================================================================
// Pair kernel: one CTA per (b,c). 256 threads / 8 warps, 2 CTAs per SM.
// =========================================================================
__global__ void __launch_bounds__(256, 2) pair_kernel(
    const int*   __restrict__ cand,
    const float* __restrict__ HW,
    const float* __restrict__ Hb,
    float*       __restrict__ out)
{
    extern __shared__ char smc[];
    bf16*  s_bm   = (bf16*) (smc + OB_BM);
    bf16*  s_amc  = (bf16*) (smc + OB_AMC);
    bf16*  s_bg2t = (bf16*) (smc + OB_BG2T);
    bf16*  s_e    = (bf16*) (smc + OB_E);
    bf16*  s_st7  = (bf16*) (smc + OB_ST7);
    bf16*  s_beta = (bf16*) (smc + OB_BETA);
    bf16*  s_alpt = (bf16*) (smc + OB_ALPT);
    int*   s_cid  = (int*)  (smc + OB_CID);
    float* sHW    = (float*)(smc + OB_HW);
    float* sRed   = (float*)(smc + OB_RED);

    const int tid  = threadIdx.x;
    const int p    = blockIdx.x;
    const int b    = p >> 6;
    const int w    = tid >> 5;
    const int lane = tid & 31;
    const int r    = lane >> 2;
    const int c    = lane & 3;

    sHW[tid] = __ldg(&HW[tid]);
    sHW[tid + 256] = __ldg(&HW[tid + 256]);
    if (tid < 64) s_cid[tid] = __ldg(&cand[p*NZ + tid]);

    // ---- P1: gather b_m rows + stage a_m chunk 0 ----
    {
        #pragma unroll
        for (int t = 0; t < 8; t++) {
            int idx = tid + 256*t;
            int z = idx >> 5, c8 = (idx & 31) * 8;
            int id = __ldg(&cand[p*NZ + z]);
            *(uint4*)(s_bm + z*P_BM + c8) = __ldg((const uint4*)(g_bm + (size_t)id*ND + c8));
        }
        int s = tid >> 1, kq = (tid & 1) * 8;
        uint4 v = __ldg((const uint4*)(g_amC + (((size_t)b*16 + 0)*NS + s)*16 + kq));
        *(uint4*)(s_amc + s*P_AMC + kq) = v;
    }
    __syncthreads();

    // ---- P3: e[s][z] = a_m @ b_m^T, chunked K (16 chunks of k16) ----
    {
        const int wm = w >> 1;       // 0..3 -> s block of 32
        const int wn = w & 1;        // 0..1 -> z block of 32
        float acc[2][4][4];
        #pragma unroll
        for (int mi=0;mi<2;mi++)
            #pragma unroll
            for (int f=0;f<4;f++)
                #pragma unroll
                for (int e=0;e<4;e++) acc[mi][f][e]=0.f;

        const int st_s = tid >> 1, st_k = (tid & 1) * 8;
        for (int t = 0; t < 16; t++) {
            if (t < 15) {
                uint4 v = __ldg((const uint4*)(g_amC + (((size_t)b*16 + t+1)*NS + st_s)*16 + st_k));
                *(uint4*)(s_amc + ((t+1)&1)*NS*P_AMC + st_s*P_AMC + st_k) = v;
            }
            const bf16* cb = s_amc + (t&1)*NS*P_AMC;
            #pragma unroll
            for (int mi = 0; mi < 2; mi++) {
                const bf16* ap = cb + (wm*32 + mi*16 + r)*P_AMC + 2*c;
                uint32_t a0=ldb(ap), a1=ldb(ap+8*P_AMC), a2=ldb(ap+8), a3=ldb(ap+8*P_AMC+8);
                #pragma unroll
                for (int f = 0; f < 4; f++) {
                    const bf16* bp = s_bm + (wn*32 + f*8 + r)*P_BM + t*16 + 2*c;
                    mmab(acc[mi][f], a0,a1,a2,a3, ldb(bp), ldb(bp+8));
                }
            }
            __syncthreads();
        }
        #pragma unroll
        for (int mi=0;mi<2;mi++)
            #pragma unroll
            for (int f=0;f<4;f++){
                int row0 = wm*32 + mi*16 + r;
                int col0 = wn*32 + f*8 + 2*c;
                *(uint32_t*)(s_e + row0*P_E + col0)     = pkf(acc[mi][f][0], acc[mi][f][1]);
                *(uint32_t*)(s_e + (row0+8)*P_E + col0) = pkf(acc[mi][f][2], acc[mi][f][3]);
            }
    }
    __syncthreads();

    // ---- P4a: beta = softmax over z (rows), 8 warps x 16 rows ----
    {
        #pragma unroll
        for (int rr = 0; rr < 16; rr++) {
            int s = w*16 + rr;
            float v0 = b2f(s_e[s*P_E + lane]);
            float v1 = b2f(s_e[s*P_E + lane + 32]);
            float mx = fmaxf(v0, v1);
            #pragma unroll
            for (int off = 16; off >= 1; off >>= 1)
                mx = fmaxf(mx, __shfl_xor_sync(0xffffffffu, mx, off));
            float e0 = expf(v0 - mx), e1 = expf(v1 - mx);
            float ss = e0 + e1;
            #pragma unroll
            for (int off = 16; off >= 1; off >>= 1)
                ss += __shfl_xor_sync(0xffffffffu, ss, off);
            float inv = 1.f / ss;
            s_beta[s*P_BETA + lane]      = __float2bfloat16_rn(e0 * inv);
            s_beta[s*P_BETA + lane + 32] = __float2bfloat16_rn(e1 * inv);
        }
    }

    // ---- P4b: alpha = softmax over s (cols) -> s_alpt transposed ----
    {
        const int z = tid >> 2, q = tid & 3;      // 4 threads per column
        float ev[32];
        float mx = -1e30f;
        #pragma unroll
        for (int i = 0; i < 32; i++) {
            ev[i] = b2f(s_e[(q*32 + i)*P_E + z]);
            mx = fmaxf(mx, ev[i]);
        }
        mx = fmaxf(mx, __shfl_xor_sync(0xffffffffu, mx, 1));
        mx = fmaxf(mx, __shfl_xor_sync(0xffffffffu, mx, 2));
        float ss = 0.f;
        #pragma unroll
        for (int i = 0; i < 32; i++) { ev[i] = expf(ev[i] - mx); ss += ev[i]; }
        ss += __shfl_xor_sync(0xffffffffu, ss, 1);
        ss += __shfl_xor_sync(0xffffffffu, ss, 2);
        float inv = 1.f / ss;
        #pragma unroll
        for (int i = 0; i < 16; i++) {
            *(uint32_t*)(s_alpt + z*P_ALPT + q*32 + 2*i) =
                pkf(ev[2*i]*inv, ev[2*i+1]*inv);
        }
    }
    __syncthreads();

    // ---- gather bbG2^T [g][z] (over dead bm) + stage st7 chunk 0 (over dead e) ----
    {
        const int g = tid;
        #pragma unroll
        for (int t = 0; t < 32; t++) {
            int z0 = 2*t;
            int id0 = s_cid[z0], id1 = s_cid[z0+1];
            bf16 v0 = __ldg(g_bg2 + (size_t)id0*ND + g);
            bf16 v1 = __ldg(g_bg2 + (size_t)id1*ND + g);
            *(uint32_t*)(s_bg2t + g*P_BG2T + z0) = pkh(v0, v1);
        }
        const uint4* src = (const uint4*)(g_aG2C + (((size_t)b*8 + 0)*ND + g)*16);
        uint4 v0 = __ldg(src), v1 = __ldg(src+1);
        *(uint4*)(s_st7 + g*P_ST7)     = v0;
        *(uint4*)(s_st7 + g*P_ST7 + 8) = v1;
    }
    __syncthreads();

    float y_local = 0.f;

    // ---- P6: y1 += sum relu(aG1 + beta @ bbG2) * HW1  (2 n64 passes) ----
    {
        const int wm = w >> 1;      // 0..3 -> s block of 32
        const int wn = w & 1;       // 0..1
        const float* aG1p = g_aG1 + (size_t)b*NS*ND;
        #pragma unroll
        for (int pass = 0; pass < 2; pass++){
            int nb = wn*128 + pass*64;
            float acc[2][8][4];
            #pragma unroll
            for (int mi=0;mi<2;mi++)
                #pragma unroll
                for (int f=0;f<8;f++)
                    #pragma unroll
                    for (int e=0;e<4;e++) acc[mi][f][e]=0.f;
            #pragma unroll
            for (int kz = 0; kz < 4; kz++) {
                uint32_t afr[2][4];
                #pragma unroll
                for (int mi = 0; mi < 2; mi++) {
                    const bf16* ap = s_beta + (wm*32 + mi*16 + r)*P_BETA + kz*16 + 2*c;
                    afr[mi][0]=ldb(ap); afr[mi][1]=ldb(ap+8*P_BETA);
                    afr[mi][2]=ldb(ap+8); afr[mi][3]=ldb(ap+8*P_BETA+8);
                }
                #pragma unroll
                for (int f = 0; f < 8; f++) {
                    const bf16* bp = s_bg2t + (nb + f*8 + r)*P_BG2T + kz*16 + 2*c;
                    uint32_t b0 = ldb(bp), b1 = ldb(bp+8);
                    mmab(acc[0][f], afr[0][0],afr[0][1],afr[0][2],afr[0][3], b0,b1);
                    mmab(acc[1][f], afr[1][0],afr[1][1],afr[1][2],afr[1][3], b0,b1);
                }
            }
            #pragma unroll
            for (int mi=0;mi<2;mi++)
                #pragma unroll
                for (int f=0;f<8;f++){
                    int row0 = wm*32 + mi*16 + r;
                    int col0 = nb + f*8 + 2*c;
                    float2 g0 = __ldg((const float2*)(aG1p + (size_t)row0*ND + col0));
                    float2 g1 = __ldg((const float2*)(aG1p + (size_t)(row0+8)*ND + col0));
                    float h0 = sHW[col0], h1 = sHW[col0+1];
                    y_local += fmaxf(acc[mi][f][0] + g0.x, 0.f)*h0
                             + fmaxf(acc[mi][f][1] + g0.y, 0.f)*h1
                             + fmaxf(acc[mi][f][2] + g1.x, 0.f)*h0
                             + fmaxf(acc[mi][f][3] + g1.y, 0.f)*h1;
                }
        }
    }

    // ---- P7: y2 += sum relu(bG1 + alpha^T @ aG2) * HW2, chunked K over s ----
    {
        const int wm = w >> 2;      // 0..1 -> z block of 32
        const int wn = w & 3;       // 0..3 -> g block of 64
        float acc[2][8][4];
        #pragma unroll
        for (int mi=0;mi<2;mi++)
            #pragma unroll
            for (int f=0;f<8;f++){
                int row0 = wm*32 + mi*16 + r;
                int col0 = wn*64 + f*8 + 2*c;
                int id0 = s_cid[row0], id1 = s_cid[row0+8];
                float2 u0 = __ldg((const float2*)(g_bg1 + (size_t)id0*ND + col0));
                float2 u1 = __ldg((const float2*)(g_bg1 + (size_t)id1*ND + col0));
                acc[mi][f][0]=u0.x; acc[mi][f][1]=u0.y;
                acc[mi][f][2]=u1.x; acc[mi][f][3]=u1.y;
            }
        const int g = tid;
        for (int t = 0; t < 8; t++) {
            if (t < 7) {
                const uint4* src = (const uint4*)(g_aG2C + (((size_t)b*8 + t+1)*ND + g)*16);
                uint4 v0 = __ldg(src), v1 = __ldg(src+1);
                bf16* dst = s_st7 + ((t+1)&1)*ND*P_ST7 + g*P_ST7;
                *(uint4*)(dst)     = v0;
                *(uint4*)(dst + 8) = v1;
            }
            const bf16* cb = s_st7 + (t&1)*ND*P_ST7;
            uint32_t afr[2][4];
            #pragma unroll
            for (int mi = 0; mi < 2; mi++) {
                const bf16* ap = s_alpt + (wm*32 + mi*16 + r)*P_ALPT + t*16 + 2*c;
                afr[mi][0]=ldb(ap); afr[mi][1]=ldb(ap+8*P_ALPT);
                afr[mi][2]=ldb(ap+8); afr[mi][3]=ldb(ap+8*P_ALPT+8);
            }
            #pragma unroll
            for (int f = 0; f < 8; f++) {
                const bf16* bp = cb + (wn*64 + f*8 + r)*P_ST7 + 2*c;
                uint32_t b0 = ldb(bp), b1 = ldb(bp+8);
                mmab(acc[0][f], afr[0][0],afr[0][1],afr[0][2],afr[0][3], b0,b1);
                mmab(acc[1][f], afr[1][0],afr[1][1],afr[1][2],afr[1][3], b0,b1);
            }
            __syncthreads();
        }
        #pragma unroll
        for (int mi=0;mi<2;mi++)
            #pragma unroll
            for (int f=0;f<8;f++){
                int col0 = wn*64 + f*8 + 2*c;
                float h0 = sHW[256+col0], h1 = sHW[256+col0+1];
                y_local += fmaxf(acc[mi][f][0], 0.f)*h0
                         + fmaxf(acc[mi][f][1], 0.f)*h1
                         + fmaxf(acc[mi][f][2], 0.f)*h0
                         + fmaxf(acc[mi][f][3], 0.f)*h1;
            }
    }

    // ---- block reduce (8 warps) ----
    {
        #pragma unroll
        for (int off = 16; off >= 1; off >>= 1)
            y_local += __shfl_xor_sync(0xffffffffu, y_local, off);
        if (lane == 0) sRed[w] = y_local;
        __syncthreads();
        if (tid == 0) {
            float t = 0.f;
            #pragma unroll
            for (int ww = 0; ww < 8; ww++) t += sRed[ww];
            out[p] = t + __ldg(&Hb[0]);
        }
    }
}

// =========================================================================
extern "C" void kernel_launch(void* const* d_in, const int* in_sizes, int n_in,
                              void* d_out, int out_size)
{
    const int*   inptensor = (const int*)  d_in[0];
    const int*   cand      = (const int*)  d_in[1];
    const float* EmbA      = (const float*)d_in[4];
    const float* EmbB      = (const float*)d_in[5];
    const float* FW        = (const float*)d_in[6];
    const float* Fb        = (const float*)d_in[7];
    const float* GW        = (const float*)d_in[8];
    const float* Gb        = (const float*)d_in[9];
    const float* HW        = (const float*)d_in[10];
    const float* Hb        = (const float*)d_in[11];
    float*       out       = (float*)d_out;

    (void)in_sizes; (void)n_in; (void)out_size;

    const int smem1 = T_SMEM_FL * 4;
    cudaFuncSetAttribute(tables_kernel, cudaFuncAttributeMaxDynamicSharedMemorySize, smem1);
    cudaFuncSetAttribute(pair_kernel,   cudaFuncAttributeMaxDynamicSharedMemorySize, SMEM_PAIR);

    tables_kernel<<<dim3(12, 2*NB + VOP/64), 256, smem1>>>(
        inptensor, EmbA, EmbB, FW, Fb, GW, Gb);
    pair_kernel<<<NB*NC, 256, SMEM_PAIR>>>(cand, HW, Hb, out);
}

// round 12
// speedup vs baseline: 1.8063x; 1.0576x over previous
#include <cuda_runtime.h>
#include <cuda_bf16.h>
#include <cstdint>

#define NB 32
#define NC 64
#define NS 128
#define NZ 64
#define ND 256
#define VO 5000
#define VOP 5120

typedef __nv_bfloat16 bf16;

// ---- pair-kernel smem byte offsets (total 108,864 B -> 2 CTAs/SM) ----
#define OB_BM    0
#define OB_AMC   33792
#define OB_BG2T  0
#define OB_E     46080
#define OB_ST7   46080
#define OB_BETA  70656
#define OB_ALPT  89088
#define OB_CID   106496
#define OB_HW    106752
#define OB_RED   108800
#define SMEM_PAIR 108864

// pitches (bf16 elements)
#define P_BM   264
#define P_AMC  24
#define P_E    72
#define P_BETA 72
#define P_BG2T 72
#define P_ALPT 136
#define P_ST7  24

// tables kernel smem (floats)
#define TA_PITCH 260
#define TW_PITCH 264
#define T_WST_OFF (64*TA_PITCH)
#define T_SMEM_FL (64*TA_PITCH + 16*TW_PITCH)

// ---------------- device scratch ----------------
__device__ bf16  g_amC [NB*16*NS*16];  // a_m chunk-major [b][kc][s][16]
__device__ float g_aG1 [NB*NS*ND];
__device__ bf16  g_aG2C[NB*8*ND*16];   // (a@GW2)^T chunk-major [b][sc][g][16]
__device__ bf16  g_bm  [VOP*ND];
__device__ float g_bg1 [VOP*ND];
__device__ bf16  g_bg2 [VOP*ND];

// ---------------- helpers ----------------
__device__ __forceinline__ uint32_t f2t(float f){
    uint32_t u; asm("cvt.rna.tf32.f32 %0, %1;" : "=r"(u) : "f"(f)); return u;
}
__device__ __forceinline__ float rtf(float f){ return __uint_as_float(f2t(f)); }
__device__ __forceinline__ uint32_t ldu(const float* p){ return __float_as_uint(*p); }
__device__ __forceinline__ uint32_t ldb(const bf16* p){
    return *reinterpret_cast<const uint32_t*>(p);
}
__device__ __forceinline__ uint32_t pkf(float a, float b){
    __nv_bfloat162 t = __floats2bfloat162_rn(a, b);
    return *reinterpret_cast<uint32_t*>(&t);
}
__device__ __forceinline__ uint32_t pkh(bf16 a, bf16 b){
    __nv_bfloat162 t = __halves2bfloat162(a, b);
    return *reinterpret_cast<uint32_t*>(&t);
}
__device__ __forceinline__ float b2f(bf16 v){ return __bfloat162float(v); }
__device__ __forceinline__ uint32_t smaddr(const void* p){
    return (uint32_t)__cvta_generic_to_shared(p);
}
__device__ __forceinline__ void ldsm4(uint32_t& r0,uint32_t& r1,uint32_t& r2,uint32_t& r3,
                                      uint32_t a){
    asm volatile("ldmatrix.sync.aligned.m8n8.x4.shared.b16 {%0,%1,%2,%3}, [%4];"
        : "=r"(r0),"=r"(r1),"=r"(r2),"=r"(r3) : "r"(a));
}

// tf32 m16n8k8
__device__ __forceinline__ void mma8(float* d,
    uint32_t a0,uint32_t a1,uint32_t a2,uint32_t a3, uint32_t b0,uint32_t b1){
    asm volatile("mma.sync.aligned.m16n8k8.row.col.f32.tf32.tf32.f32 "
        "{%0,%1,%2,%3}, {%4,%5,%6,%7}, {%8,%9}, {%0,%1,%2,%3};\n"
        : "+f"(d[0]),"+f"(d[1]),"+f"(d[2]),"+f"(d[3])
        : "r"(a0),"r"(a1),"r"(a2),"r"(a3),"r"(b0),"r"(b1));
}
// bf16 m16n8k16
__device__ __forceinline__ void mmab(float* d,
    uint32_t a0,uint32_t a1,uint32_t a2,uint32_t a3, uint32_t b0,uint32_t b1){
    asm volatile("mma.sync.aligned.m16n8k16.row.col.f32.bf16.bf16.f32 "
        "{%0,%1,%2,%3}, {%4,%5,%6,%7}, {%8,%9}, {%0,%1,%2,%3};\n"
        : "+f"(d[0]),"+f"(d[1]),"+f"(d[2]),"+f"(d[3])
        : "r"(a0),"r"(a1),"r"(a2),"r"(a3),"r"(b0),"r"(b1));
}

// A-frag (m16k16) ldmatrix address: lanes 0-15 -> rows, lanes 16-31 -> k+8 half
__device__ __forceinline__ uint32_t a_lds_addr(const bf16* buf, int row0, int kbase,
                                               int pitch, int lane){
    int row  = row0 + (lane & 15);
    int half = lane >> 4;
    return smaddr(buf + row*pitch + kbase + half*8);
}
// B-frag x4 (two n8 tiles starting at n0): lanes 0-7 mat0(n0,k0-7), 8-15 mat1(n0,k8-15),
// 16-23 mat2(n0+8,k0-7), 24-31 mat3(n0+8,k8-15)
__device__ __forceinline__ uint32_t b_lds_addr(const bf16* buf, int n0, int kbase,
                                               int pitch, int lane){
    int nrow = n0 + (lane & 7) + ((lane >> 4) << 3);
    int half = (lane >> 3) & 1;
    return smaddr(buf + nrow*pitch + kbase + half*8);
}

// =========================================================================
// Tables kernel (tf32 mma). grid=(12, 144), 256 thr. (unchanged from R11)
// =========================================================================
__global__ void __launch_bounds__(256) tables_kernel(
    const int*   __restrict__ inptensor,
    const float* __restrict__ EmbA,
    const float* __restrict__ EmbB,
    const float* __restrict__ FW,
    const float* __restrict__ Fb,
    const float* __restrict__ GW,
    const float* __restrict__ Gb)
{
    extern __shared__ float sm[];
    float* a_tile = sm;
    float* wst    = sm + T_WST_OFF;

    const int y     = blockIdx.y;
    const int chunk = blockIdx.x;
    const int m     = chunk >> 2;
    const int gbase = (chunk & 3) * 64;
    const int tid   = threadIdx.x;
    const bool aside = (y < 2*NB);
    const int w    = tid >> 5;
    const int lane = tid & 31;
    const int r    = lane >> 2;
    const int c    = lane & 3;
    const int wm   = w >> 1;
    const int wn   = w & 1;

    if (aside) {
        const int b = y >> 1, sh = (y & 1) * 64;
        for (int s = 0; s < 64; s++) {
            int idx = __ldg(&inptensor[b*NS + sh + s]);
            a_tile[s*TA_PITCH + tid] = rtf(__ldg(&EmbA[(size_t)idx*ND + tid]));
        }
    } else {
        const int rt = y - 2*NB;
        for (int s = 0; s < 64; s++) {
            int row = rt*64 + s;
            int rr = (row < VO) ? row : 0;
            a_tile[s*TA_PITCH + tid] = rtf(__ldg(&EmbB[(size_t)rr*ND + tid]));
        }
    }
    __syncthreads();

    const float* Wsrc = (m == 0) ? FW : GW;
    const int wrow_off = (m == 2) ? 256 : 0;

    float acc[4][4];
    #pragma unroll
    for (int f = 0; f < 4; f++)
        #pragma unroll
        for (int e = 0; e < 4; e++) acc[f][e] = 0.f;

    for (int t = 0; t < 16; t++) {
        int k0 = t*16;
        #pragma unroll
        for (int q = 0; q < 4; q++) {
            int idx2 = tid + 256*q;
            int kk = idx2 >> 6, gg = idx2 & 63;
            wst[kk*TW_PITCH + gg] =
                rtf(__ldg(&Wsrc[(size_t)(k0 + kk + wrow_off)*256 + gbase + gg]));
        }
        __syncthreads();
        #pragma unroll
        for (int kh = 0; kh < 2; kh++) {
            const float* ap = a_tile + (wm*16 + r)*TA_PITCH + k0 + kh*8 + c;
            uint32_t a0 = ldu(ap), a1 = ldu(ap + 8*TA_PITCH);
            uint32_t a2 = ldu(ap + 4), a3 = ldu(ap + 8*TA_PITCH + 4);
            #pragma unroll
            for (int f = 0; f < 4; f++) {
                const float* bp = wst + (kh*8 + c)*TW_PITCH + wn*32 + f*8 + r;
                mma8(acc[f], a0,a1,a2,a3, ldu(bp), ldu(bp + 4*TW_PITCH));
            }
        }
        __syncthreads();
    }

    const int b_ = y >> 1, sh = (y & 1) * 64;
    const int rt = y - 2*NB;
    const int lr0 = wm*16 + r;

    if (m == 2 && aside) {
        bf16* tbuf = (bf16*)a_tile;     // [64 g][66 s]
        #pragma unroll
        for (int f = 0; f < 4; f++) {
            int lc = wn*32 + f*8 + c*2;
            tbuf[lc*66 + lr0]       = __float2bfloat16_rn(acc[f][0]);
            tbuf[(lc+1)*66 + lr0]   = __float2bfloat16_rn(acc[f][1]);
            tbuf[lc*66 + lr0+8]     = __float2bfloat16_rn(acc[f][2]);
            tbuf[(lc+1)*66 + lr0+8] = __float2bfloat16_rn(acc[f][3]);
        }
        __syncthreads();
        int gl = tid >> 2;
        int sc4 = tid & 3;
        int scG = (sh >> 4) + sc4;
        const uint32_t* src = (const uint32_t*)(tbuf + gl*66 + sc4*16);
        uint32_t v0=src[0],v1=src[1],v2=src[2],v3=src[3];
        uint32_t v4=src[4],v5=src[5],v6=src[6],v7=src[7];
        uint4* dst = (uint4*)(g_aG2C + (((size_t)b_*8 + scG)*ND + gbase + gl)*16);
        dst[0] = make_uint4(v0,v1,v2,v3);
        dst[1] = make_uint4(v4,v5,v6,v7);
        return;
    }

    #pragma unroll
    for (int f = 0; f < 4; f++) {
        int col = gbase + wn*32 + f*8 + c*2;
        float b0 = (m == 0) ? __ldg(&Fb[col])   : (m == 1 ? __ldg(&Gb[col])   : 0.f);
        float b1 = (m == 0) ? __ldg(&Fb[col+1]) : (m == 1 ? __ldg(&Gb[col+1]) : 0.f);
        float v00 = acc[f][0] + b0, v01 = acc[f][1] + b1;
        float v10 = acc[f][2] + b0, v11 = acc[f][3] + b1;
        if (m == 0) {
            v00 = fmaxf(v00, 0.f); v01 = fmaxf(v01, 0.f);
            v10 = fmaxf(v10, 0.f); v11 = fmaxf(v11, 0.f);
        }
        int row0 = aside ? (sh + lr0) : (rt*64 + lr0);
        int row1 = row0 + 8;
        if (m == 1) {
            float* outp = aside ? (g_aG1 + (size_t)b_*NS*ND) : g_bg1;
            *(float2*)(outp + (size_t)row0*ND + col) = make_float2(v00, v01);
            *(float2*)(outp + (size_t)row1*ND + col) = make_float2(v10, v11);
        } else if (m == 0 && aside) {
            int kc = col >> 4, kin = col & 15;
            bf16* base = g_amC + (((size_t)b_*16 + kc)*NS)*16 + kin;
            *(uint32_t*)(base + row0*16) = pkf(v00, v01);
            *(uint32_t*)(base + row1*16) = pkf(v10, v11);
        } else {
            bf16* outp = (m == 0) ? g_bm : g_bg2;
            *(uint32_t*)(outp + (size_t)row0*ND + col) = pkf(v00, v01);
            *(uint32_t*)(outp + (size_t)row1*ND + col) = pkf(v10, v11);
        }
    }
}

// =========================================================================
// Pair kernel: one CTA per (b,c). 256 threads / 8 warps, 2 CTAs per SM.
// ldmatrix fragment loads + __expf softmaxes.
// =========================================================================
__global__ void __launch_bounds__(256, 2) pair_kernel(
    const int*   __restrict__ cand,
    const float* __restrict__ HW,
    const float* __restrict__ Hb,
    float*       __restrict__ out)
{
    extern __shared__ char smc[];
    bf16*  s_bm   = (bf16*) (smc + OB_BM);
    bf16*  s_amc  = (bf16*) (smc + OB_AMC);
    bf16*  s_bg2t = (bf16*) (smc + OB_BG2T);
    bf16*  s_e    = (bf16*) (smc + OB_E);
    bf16*  s_st7  = (bf16*) (smc + OB_ST7);
    bf16*  s_beta = (bf16*) (smc + OB_BETA);
    bf16*  s_alpt = (bf16*) (smc + OB_ALPT);
    int*   s_cid  = (int*)  (smc + OB_CID);
    float* sHW    = (float*)(smc + OB_HW);
    float* sRed   = (float*)(smc + OB_RED);

    const int tid  = threadIdx.x;
    const int p    = blockIdx.x;
    const int b    = p >> 6;
    const int w    = tid >> 5;
    const int lane = tid & 31;
    const int r    = lane >> 2;
    const int c    = lane & 3;

    sHW[tid] = __ldg(&HW[tid]);
    sHW[tid + 256] = __ldg(&HW[tid + 256]);
    if (tid < 64) s_cid[tid] = __ldg(&cand[p*NZ + tid]);

    // ---- P1: gather b_m rows + stage a_m chunk 0 ----
    {
        #pragma unroll
        for (int t = 0; t < 8; t++) {
            int idx = tid + 256*t;
            int z = idx >> 5, c8 = (idx & 31) * 8;
            int id = __ldg(&cand[p*NZ + z]);
            *(uint4*)(s_bm + z*P_BM + c8) = __ldg((const uint4*)(g_bm + (size_t)id*ND + c8));
        }
        int s = tid >> 1, kq = (tid & 1) * 8;
        uint4 v = __ldg((const uint4*)(g_amC + (((size_t)b*16 + 0)*NS + s)*16 + kq));
        *(uint4*)(s_amc + s*P_AMC + kq) = v;
    }
    __syncthreads();

    // ---- P3: e[s][z] = a_m @ b_m^T, chunked K (16 chunks of k16) ----
    {
        const int wm = w >> 1;       // 0..3 -> s block of 32
        const int wn = w & 1;        // 0..1 -> z block of 32
        float acc[2][4][4];
        #pragma unroll
        for (int mi=0;mi<2;mi++)
            #pragma unroll
            for (int f=0;f<4;f++)
                #pragma unroll
                for (int e=0;e<4;e++) acc[mi][f][e]=0.f;

        const int st_s = tid >> 1, st_k = (tid & 1) * 8;
        for (int t = 0; t < 16; t++) {
            if (t < 15) {
                uint4 v = __ldg((const uint4*)(g_amC + (((size_t)b*16 + t+1)*NS + st_s)*16 + st_k));
                *(uint4*)(s_amc + ((t+1)&1)*NS*P_AMC + st_s*P_AMC + st_k) = v;
            }
            const bf16* cb = s_amc + (t&1)*NS*P_AMC;
            uint32_t af[2][4];
            #pragma unroll
            for (int mi = 0; mi < 2; mi++)
                ldsm4(af[mi][0],af[mi][1],af[mi][2],af[mi][3],
                      a_lds_addr(cb, wm*32 + mi*16, 0, P_AMC, lane));
            uint32_t bfr[4][2];
            #pragma unroll
            for (int fp = 0; fp < 2; fp++)
                ldsm4(bfr[2*fp][0],bfr[2*fp][1],bfr[2*fp+1][0],bfr[2*fp+1][1],
                      b_lds_addr(s_bm, wn*32 + fp*16, t*16, P_BM, lane));
            #pragma unroll
            for (int mi = 0; mi < 2; mi++)
                #pragma unroll
                for (int f = 0; f < 4; f++)
                    mmab(acc[mi][f], af[mi][0],af[mi][1],af[mi][2],af[mi][3],
                         bfr[f][0], bfr[f][1]);
            __syncthreads();
        }
        #pragma unroll
        for (int mi=0;mi<2;mi++)
            #pragma unroll
            for (int f=0;f<4;f++){
                int row0 = wm*32 + mi*16 + r;
                int col0 = wn*32 + f*8 + 2*c;
                *(uint32_t*)(s_e + row0*P_E + col0)     = pkf(acc[mi][f][0], acc[mi][f][1]);
                *(uint32_t*)(s_e + (row0+8)*P_E + col0) = pkf(acc[mi][f][2], acc[mi][f][3]);
            }
    }
    __syncthreads();

    // ---- P4a: beta = softmax over z (rows), 8 warps x 16 rows ----
    {
        #pragma unroll
        for (int rr = 0; rr < 16; rr++) {
            int s = w*16 + rr;
            float v0 = b2f(s_e[s*P_E + lane]);
            float v1 = b2f(s_e[s*P_E + lane + 32]);
            float mx = fmaxf(v0, v1);
            #pragma unroll
            for (int off = 16; off >= 1; off >>= 1)
                mx = fmaxf(mx, __shfl_xor_sync(0xffffffffu, mx, off));
            float e0 = __expf(v0 - mx), e1 = __expf(v1 - mx);
            float ss = e0 + e1;
            #pragma unroll
            for (int off = 16; off >= 1; off >>= 1)
                ss += __shfl_xor_sync(0xffffffffu, ss, off);
            float inv = 1.f / ss;
            s_beta[s*P_BETA + lane]      = __float2bfloat16_rn(e0 * inv);
            s_beta[s*P_BETA + lane + 32] = __float2bfloat16_rn(e1 * inv);
        }
    }

    // ---- P4b: alpha = softmax over s (cols) -> s_alpt transposed ----
    {
        const int z = tid >> 2, q = tid & 3;
        float ev[32];
        float mx = -1e30f;
        #pragma unroll
        for (int i = 0; i < 32; i++) {
            ev[i] = b2f(s_e[(q*32 + i)*P_E + z]);
            mx = fmaxf(mx, ev[i]);
        }
        mx = fmaxf(mx, __shfl_xor_sync(0xffffffffu, mx, 1));
        mx = fmaxf(mx, __shfl_xor_sync(0xffffffffu, mx, 2));
        float ss = 0.f;
        #pragma unroll
        for (int i = 0; i < 32; i++) { ev[i] = __expf(ev[i] - mx); ss += ev[i]; }
        ss += __shfl_xor_sync(0xffffffffu, ss, 1);
        ss += __shfl_xor_sync(0xffffffffu, ss, 2);
        float inv = 1.f / ss;
        #pragma unroll
        for (int i = 0; i < 16; i++) {
            *(uint32_t*)(s_alpt + z*P_ALPT + q*32 + 2*i) =
                pkf(ev[2*i]*inv, ev[2*i+1]*inv);
        }
    }
    __syncthreads();

    // ---- gather bbG2^T [g][z] (over dead bm) + stage st7 chunk 0 (over dead e) ----
    {
        const int g = tid;
        #pragma unroll
        for (int t = 0; t < 32; t++) {
            int z0 = 2*t;
            int id0 = s_cid[z0], id1 = s_cid[z0+1];
            bf16 v0 = __ldg(g_bg2 + (size_t)id0*ND + g);
            bf16 v1 = __ldg(g_bg2 + (size_t)id1*ND + g);
            *(uint32_t*)(s_bg2t + g*P_BG2T + z0) = pkh(v0, v1);
        }
        const uint4* src = (const uint4*)(g_aG2C + (((size_t)b*8 + 0)*ND + g)*16);
        uint4 v0 = __ldg(src), v1 = __ldg(src+1);
        *(uint4*)(s_st7 + g*P_ST7)     = v0;
        *(uint4*)(s_st7 + g*P_ST7 + 8) = v1;
    }
    __syncthreads();

    float y_local = 0.f;

    // ---- P6: y1 += sum relu(aG1 + beta @ bbG2) * HW1  (2 n64 passes) ----
    {
        const int wm = w >> 1;      // 0..3 -> s block of 32
        const int wn = w & 1;       // 0..1
        const float* aG1p = g_aG1 + (size_t)b*NS*ND;
        #pragma unroll
        for (int pass = 0; pass < 2; pass++){
            int nb = wn*128 + pass*64;
            float acc[2][8][4];
            #pragma unroll
            for (int mi=0;mi<2;mi++)
                #pragma unroll
                for (int f=0;f<8;f++)
                    #pragma unroll
                    for (int e=0;e<4;e++) acc[mi][f][e]=0.f;
            #pragma unroll
            for (int kz = 0; kz < 4; kz++) {
                uint32_t af[2][4];
                #pragma unroll
                for (int mi = 0; mi < 2; mi++)
                    ldsm4(af[mi][0],af[mi][1],af[mi][2],af[mi][3],
                          a_lds_addr(s_beta, wm*32 + mi*16, kz*16, P_BETA, lane));
                uint32_t bfr[8][2];
                #pragma unroll
                for (int fp = 0; fp < 4; fp++)
                    ldsm4(bfr[2*fp][0],bfr[2*fp][1],bfr[2*fp+1][0],bfr[2*fp+1][1],
                          b_lds_addr(s_bg2t, nb + fp*16, kz*16, P_BG2T, lane));
                #pragma unroll
                for (int mi = 0; mi < 2; mi++)
                    #pragma unroll
                    for (int f = 0; f < 8; f++)
                        mmab(acc[mi][f], af[mi][0],af[mi][1],af[mi][2],af[mi][3],
                             bfr[f][0], bfr[f][1]);
            }
            #pragma unroll
            for (int mi=0;mi<2;mi++)
                #pragma unroll
                for (int f=0;f<8;f++){
                    int row0 = wm*32 + mi*16 + r;
                    int col0 = nb + f*8 + 2*c;
                    float2 g0 = __ldg((const float2*)(aG1p + (size_t)row0*ND + col0));
                    float2 g1 = __ldg((const float2*)(aG1p + (size_t)(row0+8)*ND + col0));
                    float h0 = sHW[col0], h1 = sHW[col0+1];
                    y_local += fmaxf(acc[mi][f][0] + g0.x, 0.f)*h0
                             + fmaxf(acc[mi][f][1] + g0.y, 0.f)*h1
                             + fmaxf(acc[mi][f][2] + g1.x, 0.f)*h0
                             + fmaxf(acc[mi][f][3] + g1.y, 0.f)*h1;
                }
        }
    }

    // ---- P7: y2 += sum relu(bG1 + alpha^T @ aG2) * HW2, chunked K over s ----
    {
        const int wm = w >> 2;      // 0..1 -> z block of 32
        const int wn = w & 3;       // 0..3 -> g block of 64
        float acc[2][8][4];
        #pragma unroll
        for (int mi=0;mi<2;mi++)
            #pragma unroll
            for (int f=0;f<8;f++){
                int row0 = wm*32 + mi*16 + r;
                int col0 = wn*64 + f*8 + 2*c;
                int id0 = s_cid[row0], id1 = s_cid[row0+8];
                float2 u0 = __ldg((const float2*)(g_bg1 + (size_t)id0*ND + col0));
                float2 u1 = __ldg((const float2*)(g_bg1 + (size_t)id1*ND + col0));
                acc[mi][f][0]=u0.x; acc[mi][f][1]=u0.y;
                acc[mi][f][2]=u1.x; acc[mi][f][3]=u1.y;
            }
        const int g = tid;
        for (int t = 0; t < 8; t++) {
            if (t < 7) {
                const uint4* src = (const uint4*)(g_aG2C + (((size_t)b*8 + t+1)*ND + g)*16);
                uint4 v0 = __ldg(src), v1 = __ldg(src+1);
                bf16* dst = s_st7 + ((t+1)&1)*ND*P_ST7 + g*P_ST7;
                *(uint4*)(dst)     = v0;
                *(uint4*)(dst + 8) = v1;
            }
            const bf16* cb = s_st7 + (t&1)*ND*P_ST7;
            uint32_t af[2][4];
            #pragma unroll
            for (int mi = 0; mi < 2; mi++)
                ldsm4(af[mi][0],af[mi][1],af[mi][2],af[mi][3],
                      a_lds_addr(s_alpt, wm*32 + mi*16, t*16, P_ALPT, lane));
            uint32_t bfr[8][2];
            #pragma unroll
            for (int fp = 0; fp < 4; fp++)
                ldsm4(bfr[2*fp][0],bfr[2*fp][1],bfr[2*fp+1][0],bfr[2*fp+1][1],
                      b_lds_addr(cb, wn*64 + fp*16, 0, P_ST7, lane));
            #pragma unroll
            for (int mi = 0; mi < 2; mi++)
                #pragma unroll
                for (int f = 0; f < 8; f++)
                    mmab(acc[mi][f], af[mi][0],af[mi][1],af[mi][2],af[mi][3],
                         bfr[f][0], bfr[f][1]);
            __syncthreads();
        }
        #pragma unroll
        for (int mi=0;mi<2;mi++)
            #pragma unroll
            for (int f=0;f<8;f++){
                int col0 = wn*64 + f*8 + 2*c;
                float h0 = sHW[256+col0], h1 = sHW[256+col0+1];
                y_local += fmaxf(acc[mi][f][0], 0.f)*h0
                         + fmaxf(acc[mi][f][1], 0.f)*h1
                         + fmaxf(acc[mi][f][2], 0.f)*h0
                         + fmaxf(acc[mi][f][3], 0.f)*h1;
            }
    }

    // ---- block reduce (8 warps) ----
    {
        #pragma unroll
        for (int off = 16; off >= 1; off >>= 1)
            y_local += __shfl_xor_sync(0xffffffffu, y_local, off);
        if (lane == 0) sRed[w] = y_local;
        __syncthreads();
        if (tid == 0) {
            float t = 0.f;
            #pragma unroll
            for (int ww = 0; ww < 8; ww++) t += sRed[ww];
            out[p] = t + __ldg(&Hb[0]);
        }
    }
}

// =========================================================================
extern "C" void kernel_launch(void* const* d_in, const int* in_sizes, int n_in,
                              void* d_out, int out_size)
{
    const int*   inptensor = (const int*)  d_in[0];
    const int*   cand      = (const int*)  d_in[1];
    const float* EmbA      = (const float*)d_in[4];
    const float* EmbB      = (const float*)d_in[5];
    const float* FW        = (const float*)d_in[6];
    const float* Fb        = (const float*)d_in[7];
    const float* GW        = (const float*)d_in[8];
    const float* Gb        = (const float*)d_in[9];
    const float* HW        = (const float*)d_in[10];
    const float* Hb        = (const float*)d_in[11];
    float*       out       = (float*)d_out;

    (void)in_sizes; (void)n_in; (void)out_size;

    const int smem1 = T_SMEM_FL * 4;
    cudaFuncSetAttribute(tables_kernel, cudaFuncAttributeMaxDynamicSharedMemorySize, smem1);
    cudaFuncSetAttribute(pair_kernel,   cudaFuncAttributeMaxDynamicSharedMemorySize, SMEM_PAIR);

    tables_kernel<<<dim3(12, 2*NB + VOP/64), 256, smem1>>>(
        inptensor, EmbA, EmbB, FW, Fb, GW, Gb);
    pair_kernel<<<NB*NC, 256, SMEM_PAIR>>>(cand, HW, Hb, out);
}

// round 14
// speedup vs baseline: 1.8645x; 1.0323x over previous
#include <cuda_runtime.h>
#include <cuda_bf16.h>
#include <cstdint>

#define NB 32
#define NC 64
#define NS 128
#define NZ 64
#define ND 256
#define VO 5000
#define VOP 5120

typedef __nv_bfloat16 bf16;

// ---- pair-kernel smem byte offsets (103,712 B -> 2 CTAs/SM) ----
// Phase A (P1/P3):  am [128][264]b @0 (67584) | bm [64][264]b @67584 (33792, ends 101376)
// Phase B:          beta @0 (18432) | alpt @18432 (17408) | bg2t @35840 (36864)
//                   | st7 2x[256][24]b @72704 (24576, ends 97280)
//                   | e [128][72]b @72704 (18432) overlays st7 (time-disjoint)
#define OB_AM    0
#define OB_BM    67584
#define OB_BETA  0
#define OB_ALPT  18432
#define OB_BG2T  35840
#define OB_ST7   72704
#define OB_E     72704
#define OB_CID   101376
#define OB_HW    101632
#define OB_RED   103680
#define SMEM_PAIR 103712

// pitches (bf16 elements)
#define P_AM   264
#define P_BM   264
#define P_E    72
#define P_BETA 72
#define P_BG2T 72
#define P_ALPT 136
#define P_ST7  24

// tables kernel smem (floats)
#define TA_PITCH 260
#define TW_PITCH 264
#define T_WST_OFF (64*TA_PITCH)
#define T_SMEM_FL (64*TA_PITCH + 16*TW_PITCH)

// ---------------- device scratch ----------------
__device__ bf16  g_am  [NB*NS*ND];     // relu(a@FW+Fb) row-major [b][s][k]
__device__ float g_aG1 [NB*NS*ND];     // exact a@GW1+Gb [b][s][g]
__device__ bf16  g_aG2C[NB*8*ND*16];   // (a@GW2)^T chunk-major [b][sc][g][16]
__device__ bf16  g_bm  [VOP*ND];
__device__ float g_bg1 [VOP*ND];
__device__ bf16  g_bg2 [VOP*ND];

// ---------------- helpers ----------------
__device__ __forceinline__ uint32_t f2t(float f){
    uint32_t u; asm("cvt.rna.tf32.f32 %0, %1;" : "=r"(u) : "f"(f)); return u;
}
__device__ __forceinline__ float rtf(float f){ return __uint_as_float(f2t(f)); }
__device__ __forceinline__ uint32_t ldu(const float* p){ return __float_as_uint(*p); }
__device__ __forceinline__ uint32_t pkf(float a, float b){
    __nv_bfloat162 t = __floats2bfloat162_rn(a, b);
    return *reinterpret_cast<uint32_t*>(&t);
}
__device__ __forceinline__ uint32_t pkh(bf16 a, bf16 b){
    __nv_bfloat162 t = __halves2bfloat162(a, b);
    return *reinterpret_cast<uint32_t*>(&t);
}
__device__ __forceinline__ float b2f(bf16 v){ return __bfloat162float(v); }
__device__ __forceinline__ uint32_t smaddr(const void* p){
    return (uint32_t)__cvta_generic_to_shared(p);
}
__device__ __forceinline__ void ldsm4(uint32_t& r0,uint32_t& r1,uint32_t& r2,uint32_t& r3,
                                      uint32_t a){
    asm volatile("ldmatrix.sync.aligned.m8n8.x4.shared.b16 {%0,%1,%2,%3}, [%4];"
        : "=r"(r0),"=r"(r1),"=r"(r2),"=r"(r3) : "r"(a));
}

// tf32 m16n8k8
__device__ __forceinline__ void mma8(float* d,
    uint32_t a0,uint32_t a1,uint32_t a2,uint32_t a3, uint32_t b0,uint32_t b1){
    asm volatile("mma.sync.aligned.m16n8k8.row.col.f32.tf32.tf32.f32 "
        "{%0,%1,%2,%3}, {%4,%5,%6,%7}, {%8,%9}, {%0,%1,%2,%3};\n"
        : "+f"(d[0]),"+f"(d[1]),"+f"(d[2]),"+f"(d[3])
        : "r"(a0),"r"(a1),"r"(a2),"r"(a3),"r"(b0),"r"(b1));
}
// bf16 m16n8k16
__device__ __forceinline__ void mmab(float* d,
    uint32_t a0,uint32_t a1,uint32_t a2,uint32_t a3, uint32_t b0,uint32_t b1){
    asm volatile("mma.sync.aligned.m16n8k16.row.col.f32.bf16.bf16.f32 "
        "{%0,%1,%2,%3}, {%4,%5,%6,%7}, {%8,%9}, {%0,%1,%2,%3};\n"
        : "+f"(d[0]),"+f"(d[1]),"+f"(d[2]),"+f"(d[3])
        : "r"(a0),"r"(a1),"r"(a2),"r"(a3),"r"(b0),"r"(b1));
}

// A-frag (m16k16) ldmatrix: lanes 0-15 rows, 16-31 k+8 half (validated R12)
__device__ __forceinline__ uint32_t a_lds_addr(const bf16* buf, int row0, int kbase,
                                               int pitch, int lane){
    int row  = row0 + (lane & 15);
    int half = lane >> 4;
    return smaddr(buf + row*pitch + kbase + half*8);
}
// B-frag x4 (two n8 tiles) (validated R12)
__device__ __forceinline__ uint32_t b_lds_addr(const bf16* buf, int n0, int kbase,
                                               int pitch, int lane){
    int nrow = n0 + (lane & 7) + ((lane >> 4) << 3);
    int half = (lane >> 3) & 1;
    return smaddr(buf + nrow*pitch + kbase + half*8);
}

// =========================================================================
// Tables kernel (tf32 mma). grid=(12, 144), 256 thr. (unchanged from R12/R13)
// =========================================================================
__global__ void __launch_bounds__(256) tables_kernel(
    const int*   __restrict__ inptensor,
    const float* __restrict__ EmbA,
    const float* __restrict__ EmbB,
    const float* __restrict__ FW,
    const float* __restrict__ Fb,
    const float* __restrict__ GW,
    const float* __restrict__ Gb)
{
    extern __shared__ float sm[];
    float* a_tile = sm;
    float* wst    = sm + T_WST_OFF;

    const int y     = blockIdx.y;
    const int chunk = blockIdx.x;
    const int m     = chunk >> 2;
    const int gbase = (chunk & 3) * 64;
    const int tid   = threadIdx.x;
    const bool aside = (y < 2*NB);
    const int w    = tid >> 5;
    const int lane = tid & 31;
    const int r    = lane >> 2;
    const int c    = lane & 3;
    const int wm   = w >> 1;
    const int wn   = w & 1;

    if (aside) {
        const int b = y >> 1, sh = (y & 1) * 64;
        for (int s = 0; s < 64; s++) {
            int idx = __ldg(&inptensor[b*NS + sh + s]);
            a_tile[s*TA_PITCH + tid] = rtf(__ldg(&EmbA[(size_t)idx*ND + tid]));
        }
    } else {
        const int rt = y - 2*NB;
        for (int s = 0; s < 64; s++) {
            int row = rt*64 + s;
            int rr = (row < VO) ? row : 0;
            a_tile[s*TA_PITCH + tid] = rtf(__ldg(&EmbB[(size_t)rr*ND + tid]));
        }
    }
    __syncthreads();

    const float* Wsrc = (m == 0) ? FW : GW;
    const int wrow_off = (m == 2) ? 256 : 0;

    float acc[4][4];
    #pragma unroll
    for (int f = 0; f < 4; f++)
        #pragma unroll
        for (int e = 0; e < 4; e++) acc[f][e] = 0.f;

    for (int t = 0; t < 16; t++) {
        int k0 = t*16;
        #pragma unroll
        for (int q = 0; q < 4; q++) {
            int idx2 = tid + 256*q;
            int kk = idx2 >> 6, gg = idx2 & 63;
            wst[kk*TW_PITCH + gg] =
                rtf(__ldg(&Wsrc[(size_t)(k0 + kk + wrow_off)*256 + gbase + gg]));
        }
        __syncthreads();
        #pragma unroll
        for (int kh = 0; kh < 2; kh++) {
            const float* ap = a_tile + (wm*16 + r)*TA_PITCH + k0 + kh*8 + c;
            uint32_t a0 = ldu(ap), a1 = ldu(ap + 8*TA_PITCH);
            uint32_t a2 = ldu(ap + 4), a3 = ldu(ap + 8*TA_PITCH + 4);
            #pragma unroll
            for (int f = 0; f < 4; f++) {
                const float* bp = wst + (kh*8 + c)*TW_PITCH + wn*32 + f*8 + r;
                mma8(acc[f], a0,a1,a2,a3, ldu(bp), ldu(bp + 4*TW_PITCH));
            }
        }
        __syncthreads();
    }

    const int b_ = y >> 1, sh = (y & 1) * 64;
    const int rt = y - 2*NB;
    const int lr0 = wm*16 + r;

    if (m == 2 && aside) {
        bf16* tbuf = (bf16*)a_tile;     // [64 g][66 s]
        #pragma unroll
        for (int f = 0; f < 4; f++) {
            int lc = wn*32 + f*8 + c*2;
            tbuf[lc*66 + lr0]       = __float2bfloat16_rn(acc[f][0]);
            tbuf[(lc+1)*66 + lr0]   = __float2bfloat16_rn(acc[f][1]);
            tbuf[lc*66 + lr0+8]     = __float2bfloat16_rn(acc[f][2]);
            tbuf[(lc+1)*66 + lr0+8] = __float2bfloat16_rn(acc[f][3]);
        }
        __syncthreads();
        int gl = tid >> 2;
        int sc4 = tid & 3;
        int scG = (sh >> 4) + sc4;
        const uint32_t* src = (const uint32_t*)(tbuf + gl*66 + sc4*16);
        uint32_t v0=src[0],v1=src[1],v2=src[2],v3=src[3];
        uint32_t v4=src[4],v5=src[5],v6=src[6],v7=src[7];
        uint4* dst = (uint4*)(g_aG2C + (((size_t)b_*8 + scG)*ND + gbase + gl)*16);
        dst[0] = make_uint4(v0,v1,v2,v3);
        dst[1] = make_uint4(v4,v5,v6,v7);
        return;
    }

    #pragma unroll
    for (int f = 0; f < 4; f++) {
        int col = gbase + wn*32 + f*8 + c*2;
        float b0 = (m == 0) ? __ldg(&Fb[col])   : (m == 1 ? __ldg(&Gb[col])   : 0.f);
        float b1 = (m == 0) ? __ldg(&Fb[col+1]) : (m == 1 ? __ldg(&Gb[col+1]) : 0.f);
        float v00 = acc[f][0] + b0, v01 = acc[f][1] + b1;
        float v10 = acc[f][2] + b0, v11 = acc[f][3] + b1;
        if (m == 0) {
            v00 = fmaxf(v00, 0.f); v01 = fmaxf(v01, 0.f);
            v10 = fmaxf(v10, 0.f); v11 = fmaxf(v11, 0.f);
        }
        int row0 = aside ? (sh + lr0) : (rt*64 + lr0);
        int row1 = row0 + 8;
        if (m == 1) {
            float* outp = aside ? (g_aG1 + (size_t)b_*NS*ND) : g_bg1;
            *(float2*)(outp + (size_t)row0*ND + col) = make_float2(v00, v01);
            *(float2*)(outp + (size_t)row1*ND + col) = make_float2(v10, v11);
        } else {
            bf16* outp = (m == 0) ? (aside ? (g_am + (size_t)b_*NS*ND) : g_bm)
                                  : g_bg2;
            *(uint32_t*)(outp + (size_t)row0*ND + col) = pkf(v00, v01);
            *(uint32_t*)(outp + (size_t)row1*ND + col) = pkf(v10, v11);
        }
    }
}

// =========================================================================
// Pair kernel: one CTA per (b,c). 256 threads / 8 warps, 2 CTAs per SM.
// a_m fully resident in smem; P3 sync-free.
// =========================================================================
__global__ void __launch_bounds__(256, 2) pair_kernel(
    const int*   __restrict__ cand,
    const float* __restrict__ HW,
    const float* __restrict__ Hb,
    float*       __restrict__ out)
{
    extern __shared__ char smc[];
    bf16*  s_am   = (bf16*) (smc + OB_AM);
    bf16*  s_bm   = (bf16*) (smc + OB_BM);
    bf16*  s_e    = (bf16*) (smc + OB_E);
    bf16*  s_beta = (bf16*) (smc + OB_BETA);
    bf16*  s_alpt = (bf16*) (smc + OB_ALPT);
    bf16*  s_bg2t = (bf16*) (smc + OB_BG2T);
    bf16*  s_st7  = (bf16*) (smc + OB_ST7);
    int*   s_cid  = (int*)  (smc + OB_CID);
    float* sHW    = (float*)(smc + OB_HW);
    float* sRed   = (float*)(smc + OB_RED);

    const int tid  = threadIdx.x;
    const int p    = blockIdx.x;
    const int b    = p >> 6;
    const int w    = tid >> 5;
    const int lane = tid & 31;
    const int r    = lane >> 2;
    const int c    = lane & 3;

    sHW[tid] = __ldg(&HW[tid]);
    sHW[tid + 256] = __ldg(&HW[tid + 256]);
    if (tid < 64) s_cid[tid] = __ldg(&cand[p*NZ + tid]);

    // ---- P1: stage full a_m (128x256) + gather b_m rows ----
    {
        const uint4* src = (const uint4*)(g_am + (size_t)b*NS*ND);   // 4096 uint4
        #pragma unroll
        for (int t = 0; t < 16; t++) {
            int idx = tid + 256*t;
            int row = idx >> 5, c8 = (idx & 31) * 8;
            *(uint4*)(s_am + row*P_AM + c8) = __ldg(&src[idx]);
        }
        #pragma unroll
        for (int t = 0; t < 8; t++) {
            int idx = tid + 256*t;
            int z = idx >> 5, c8 = (idx & 31) * 8;
            int id = __ldg(&cand[p*NZ + z]);
            *(uint4*)(s_bm + z*P_BM + c8) = __ldg((const uint4*)(g_bm + (size_t)id*ND + c8));
        }
    }
    __syncthreads();

    // ---- P3: e[s][z] = a_m @ b_m^T, sync-free (K=256, 16 k16 iters) ----
    float eacc[2][4][4];
    {
        const int wm = w >> 1;       // 0..3 -> s block of 32
        const int wn = w & 1;        // 0..1 -> z block of 32
        #pragma unroll
        for (int mi=0;mi<2;mi++)
            #pragma unroll
            for (int f=0;f<4;f++)
                #pragma unroll
                for (int e=0;e<4;e++) eacc[mi][f][e]=0.f;

        #pragma unroll 4
        for (int ks = 0; ks < 16; ks++) {
            uint32_t af[2][4];
            #pragma unroll
            for (int mi = 0; mi < 2; mi++)
                ldsm4(af[mi][0],af[mi][1],af[mi][2],af[mi][3],
                      a_lds_addr(s_am, wm*32 + mi*16, ks*16, P_AM, lane));
            uint32_t bfr[4][2];
            #pragma unroll
            for (int fp = 0; fp < 2; fp++)
                ldsm4(bfr[2*fp][0],bfr[2*fp][1],bfr[2*fp+1][0],bfr[2*fp+1][1],
                      b_lds_addr(s_bm, wn*32 + fp*16, ks*16, P_BM, lane));
            #pragma unroll
            for (int mi = 0; mi < 2; mi++)
                #pragma unroll
                for (int f = 0; f < 4; f++)
                    mmab(eacc[mi][f], af[mi][0],af[mi][1],af[mi][2],af[mi][3],
                         bfr[f][0], bfr[f][1]);
        }
    }
    __syncthreads();   // am/bm dead -> Phase B overlays become writable

    // write e (bf16)
    {
        const int wm = w >> 1;
        const int wn = w & 1;
        #pragma unroll
        for (int mi=0;mi<2;mi++)
            #pragma unroll
            for (int f=0;f<4;f++){
                int row0 = wm*32 + mi*16 + r;
                int col0 = wn*32 + f*8 + 2*c;
                *(uint32_t*)(s_e + row0*P_E + col0)     = pkf(eacc[mi][f][0], eacc[mi][f][1]);
                *(uint32_t*)(s_e + (row0+8)*P_E + col0) = pkf(eacc[mi][f][2], eacc[mi][f][3]);
            }
    }
    __syncthreads();

    // ---- P4a: beta = softmax over z (rows), 8 warps x 16 rows ----
    {
        #pragma unroll
        for (int rr = 0; rr < 16; rr++) {
            int s = w*16 + rr;
            float v0 = b2f(s_e[s*P_E + lane]);
            float v1 = b2f(s_e[s*P_E + lane + 32]);
            float mx = fmaxf(v0, v1);
            #pragma unroll
            for (int off = 16; off >= 1; off >>= 1)
                mx = fmaxf(mx, __shfl_xor_sync(0xffffffffu, mx, off));
            float e0 = __expf(v0 - mx), e1 = __expf(v1 - mx);
            float ss = e0 + e1;
            #pragma unroll
            for (int off = 16; off >= 1; off >>= 1)
                ss += __shfl_xor_sync(0xffffffffu, ss, off);
            float inv = 1.f / ss;
            s_beta[s*P_BETA + lane]      = __float2bfloat16_rn(e0 * inv);
            s_beta[s*P_BETA + lane + 32] = __float2bfloat16_rn(e1 * inv);
        }
    }

    // ---- P4b: alpha = softmax over s (cols) -> s_alpt transposed ----
    {
        const int z = tid >> 2, q = tid & 3;
        float ev[32];
        float mx = -1e30f;
        #pragma unroll
        for (int i = 0; i < 32; i++) {
            ev[i] = b2f(s_e[(q*32 + i)*P_E + z]);
            mx = fmaxf(mx, ev[i]);
        }
        mx = fmaxf(mx, __shfl_xor_sync(0xffffffffu, mx, 1));
        mx = fmaxf(mx, __shfl_xor_sync(0xffffffffu, mx, 2));
        float ss = 0.f;
        #pragma unroll
        for (int i = 0; i < 32; i++) { ev[i] = __expf(ev[i] - mx); ss += ev[i]; }
        ss += __shfl_xor_sync(0xffffffffu, ss, 1);
        ss += __shfl_xor_sync(0xffffffffu, ss, 2);
        float inv = 1.f / ss;
        #pragma unroll
        for (int i = 0; i < 16; i++) {
            *(uint32_t*)(s_alpt + z*P_ALPT + q*32 + 2*i) =
                pkf(ev[2*i]*inv, ev[2*i+1]*inv);
        }
    }
    __syncthreads();   // e dead -> st7 region writable

    // ---- gather bbG2^T [g][z] + stage st7 chunk 0 ----
    {
        const int g = tid;
        #pragma unroll
        for (int t = 0; t < 32; t++) {
            int z0 = 2*t;
            int id0 = s_cid[z0], id1 = s_cid[z0+1];
            bf16 v0 = __ldg(g_bg2 + (size_t)id0*ND + g);
            bf16 v1 = __ldg(g_bg2 + (size_t)id1*ND + g);
            *(uint32_t*)(s_bg2t + g*P_BG2T + z0) = pkh(v0, v1);
        }
        const uint4* src = (const uint4*)(g_aG2C + (((size_t)b*8 + 0)*ND + g)*16);
        uint4 v0 = __ldg(src), v1 = __ldg(src+1);
        *(uint4*)(s_st7 + g*P_ST7)     = v0;
        *(uint4*)(s_st7 + g*P_ST7 + 8) = v1;
    }
    __syncthreads();

    float y_local = 0.f;

    // ---- P6: y1 += sum relu(aG1 + beta @ bbG2) * HW1  (2 n64 passes) ----
    {
        const int wm = w >> 1;      // 0..3 -> s block of 32
        const int wn = w & 1;       // 0..1
        const float* aG1p = g_aG1 + (size_t)b*NS*ND;
        #pragma unroll
        for (int pass = 0; pass < 2; pass++){
            int nb = wn*128 + pass*64;
            float acc[2][8][4];
            #pragma unroll
            for (int mi=0;mi<2;mi++)
                #pragma unroll
                for (int f=0;f<8;f++)
                    #pragma unroll
                    for (int e=0;e<4;e++) acc[mi][f][e]=0.f;
            #pragma unroll
            for (int kz = 0; kz < 4; kz++) {
                uint32_t af[2][4];
                #pragma unroll
                for (int mi = 0; mi < 2; mi++)
                    ldsm4(af[mi][0],af[mi][1],af[mi][2],af[mi][3],
                          a_lds_addr(s_beta, wm*32 + mi*16, kz*16, P_BETA, lane));
                uint32_t bfr[8][2];
                #pragma unroll
                for (int fp = 0; fp < 4; fp++)
                    ldsm4(bfr[2*fp][0],bfr[2*fp][1],bfr[2*fp+1][0],bfr[2*fp+1][1],
                          b_lds_addr(s_bg2t, nb + fp*16, kz*16, P_BG2T, lane));
                #pragma unroll
                for (int mi = 0; mi < 2; mi++)
                    #pragma unroll
                    for (int f = 0; f < 8; f++)
                        mmab(acc[mi][f], af[mi][0],af[mi][1],af[mi][2],af[mi][3],
                             bfr[f][0], bfr[f][1]);
            }
            #pragma unroll
            for (int mi=0;mi<2;mi++)
                #pragma unroll
                for (int f=0;f<8;f++){
                    int row0 = wm*32 + mi*16 + r;
                    int col0 = nb + f*8 + 2*c;
                    float2 g0 = __ldg((const float2*)(aG1p + (size_t)row0*ND + col0));
                    float2 g1 = __ldg((const float2*)(aG1p + (size_t)(row0+8)*ND + col0));
                    float h0 = sHW[col0], h1 = sHW[col0+1];
                    y_local += fmaxf(acc[mi][f][0] + g0.x, 0.f)*h0
                             + fmaxf(acc[mi][f][1] + g0.y, 0.f)*h1
                             + fmaxf(acc[mi][f][2] + g1.x, 0.f)*h0
                             + fmaxf(acc[mi][f][3] + g1.y, 0.f)*h1;
                }
        }
    }

    // ---- P7: y2 += sum relu(bG1 + alpha^T @ aG2) * HW2, chunked K over s ----
    {
        const int wm = w >> 2;      // 0..1 -> z block of 32
        const int wn = w & 3;       // 0..3 -> g block of 64
        float acc[2][8][4];
        #pragma unroll
        for (int mi=0;mi<2;mi++)
            #pragma unroll
            for (int f=0;f<8;f++){
                int row0 = wm*32 + mi*16 + r;
                int col0 = wn*64 + f*8 + 2*c;
                int id0 = s_cid[row0], id1 = s_cid[row0+8];
                float2 u0 = __ldg((const float2*)(g_bg1 + (size_t)id0*ND + col0));
                float2 u1 = __ldg((const float2*)(g_bg1 + (size_t)id1*ND + col0));
                acc[mi][f][0]=u0.x; acc[mi][f][1]=u0.y;
                acc[mi][f][2]=u1.x; acc[mi][f][3]=u1.y;
            }
        const int g = tid;
        for (int t = 0; t < 8; t++) {
            if (t < 7) {
                const uint4* src = (const uint4*)(g_aG2C + (((size_t)b*8 + t+1)*ND + g)*16);
                uint4 v0 = __ldg(src), v1 = __ldg(src+1);
                bf16* dst = s_st7 + ((t+1)&1)*ND*P_ST7 + g*P_ST7;
                *(uint4*)(dst)     = v0;
                *(uint4*)(dst + 8) = v1;
            }
            const bf16* cb = s_st7 + (t&1)*ND*P_ST7;
            uint32_t af[2][4];
            #pragma unroll
            for (int mi = 0; mi < 2; mi++)
                ldsm4(af[mi][0],af[mi][1],af[mi][2],af[mi][3],
                      a_lds_addr(s_alpt, wm*32 + mi*16, t*16, P_ALPT, lane));
            uint32_t bfr[8][2];
            #pragma unroll
            for (int fp = 0; fp < 4; fp++)
                ldsm4(bfr[2*fp][0],bfr[2*fp][1],bfr[2*fp+1][0],bfr[2*fp+1][1],
                      b_lds_addr(cb, wn*64 + fp*16, 0, P_ST7, lane));
            #pragma unroll
            for (int mi = 0; mi < 2; mi++)
                #pragma unroll
                for (int f = 0; f < 8; f++)
                    mmab(acc[mi][f], af[mi][0],af[mi][1],af[mi][2],af[mi][3],
                         bfr[f][0], bfr[f][1]);
            __syncthreads();
        }
        #pragma unroll
        for (int mi=0;mi<2;mi++)
            #pragma unroll
            for (int f=0;f<8;f++){
                int col0 = wn*64 + f*8 + 2*c;
                float h0 = sHW[256+col0], h1 = sHW[256+col0+1];
                y_local += fmaxf(acc[mi][f][0], 0.f)*h0
                         + fmaxf(acc[mi][f][1], 0.f)*h1
                         + fmaxf(acc[mi][f][2], 0.f)*h0
                         + fmaxf(acc[mi][f][3], 0.f)*h1;
            }
    }

    // ---- block reduce (8 warps) ----
    {
        #pragma unroll
        for (int off = 16; off >= 1; off >>= 1)
            y_local += __shfl_xor_sync(0xffffffffu, y_local, off);
        if (lane == 0) sRed[w] = y_local;
        __syncthreads();
        if (tid == 0) {
            float t = 0.f;
            #pragma unroll
            for (int ww = 0; ww < 8; ww++) t += sRed[ww];
            out[p] = t + __ldg(&Hb[0]);
        }
    }
}

// =========================================================================
extern "C" void kernel_launch(void* const* d_in, const int* in_sizes, int n_in,
                              void* d_out, int out_size)
{
    const int*   inptensor = (const int*)  d_in[0];
    const int*   cand      = (const int*)  d_in[1];
    const float* EmbA      = (const float*)d_in[4];
    const float* EmbB      = (const float*)d_in[5];
    const float* FW        = (const float*)d_in[6];
    const float* Fb        = (const float*)d_in[7];
    const float* GW        = (const float*)d_in[8];
    const float* Gb        = (const float*)d_in[9];
    const float* HW        = (const float*)d_in[10];
    const float* Hb        = (const float*)d_in[11];
    float*       out       = (float*)d_out;

    (void)in_sizes; (void)n_in; (void)out_size;

    const int smem1 = T_SMEM_FL * 4;
    cudaFuncSetAttribute(tables_kernel, cudaFuncAttributeMaxDynamicSharedMemorySize, smem1);
    cudaFuncSetAttribute(pair_kernel,   cudaFuncAttributeMaxDynamicSharedMemorySize, SMEM_PAIR);

    tables_kernel<<<dim3(12, 2*NB + VOP/64), 256, smem1>>>(
        inptensor, EmbA, EmbB, FW, Fb, GW, Gb);
    pair_kernel<<<NB*NC, 256, SMEM_PAIR>>>(cand, HW, Hb, out);
}